// round 14
// baseline (speedup 1.0000x reference)
#include <cuda_runtime.h>
#include <cuda_bf16.h>
#include <math.h>
#include <stdint.h>

#define NN 50000
#define NE 800000
#define NSLICE (NE / 16)   // 50000 16-edge warp-slices

// ---------------- scratch (static device globals, no allocation) ----------------
__device__ float g_agg[(size_t)NN * 64];
__device__ float g_cnt[NN];
__device__ float g_P1[(size_t)NN * 64];
__device__ float g_P2[(size_t)NN * 64];

__global__ void zero_k() {
    int i = blockIdx.x * blockDim.x + threadIdx.x;
    int stride = gridDim.x * blockDim.x;
    for (int j = i; j < NN * 64; j += stride) g_agg[j] = 0.0f;
    for (int j = i; j < NN; j += stride) g_cnt[j] = 0.0f;
}

// no-op: keeps edge_k in the ncu-captured launch slot (absolute idx 3)
__global__ void noop_k() {}

// MUFU-free softplus: all FFMA/ALU, rel err ~1.5e-6.
__device__ __forceinline__ float softplus_f(float v) {
    float w = -fabsf(v);
    float t = fmaxf(w * 1.4426950408889634f, -120.0f);
    float nf = rintf(t);
    float f = t - nf;
    float g = f * 0.6931471805599453f;
    float p = 1.388888889e-3f;
    p = p * g + 8.333333333e-3f;
    p = p * g + 4.166666667e-2f;
    p = p * g + 1.666666667e-1f;
    p = p * g + 0.5f;
    p = p * g + 1.0f;
    p = p * g + 1.0f;
    int ni = __float2int_rn(nf);
    float scale = __int_as_float((127 + ni) << 23);
    float u = p * scale;
    float d = 2.0f + u;
    float y = 0.8249f - 0.16666667f * d;
    y = y * (2.0f - d * y);
    y = y * (2.0f - d * y);
    float z = u * y;
    float z2 = z * z;
    float q = 0.11111111f;
    q = q * z2 + 0.14285714f;
    q = q * z2 + 0.2f;
    q = q * z2 + 0.33333333f;
    q = q * z2 + 1.0f;
    float lg = 2.0f * z * q;
    return fmaxf(v, 0.0f) + lg;
}

__device__ __forceinline__ uint32_t smem_u32(const void* p) {
    uint32_t a;
    asm("{ .reg .u64 t; cvta.to.shared.u64 t, %1; cvt.u32.u64 %0, t; }" : "=r"(a) : "l"(p));
    return a;
}

__device__ __forceinline__ void red_add_v4(float* addr, float a, float b, float c, float d) {
    asm volatile("red.global.add.v4.f32 [%0], {%1, %2, %3, %4};"
                 :: "l"(addr), "f"(a), "f"(b), "f"(c), "f"(d) : "memory");
}

__device__ __forceinline__ void cp16(uint32_t dst, const void* src) {
    asm volatile("cp.async.cg.shared.global [%0], [%1], 16;" :: "r"(dst), "l"(src) : "memory");
}
#define CP_COMMIT() asm volatile("cp.async.commit_group;" ::: "memory")
#define CP_WAIT1()  asm volatile("cp.async.wait_group 1;" ::: "memory")

__device__ __forceinline__ uint32_t pack_hi(float a, float b, float& ra, float& rb) {
    __nv_bfloat16 ha = __float2bfloat16(a);
    __nv_bfloat16 hb = __float2bfloat16(b);
    ra = a - __bfloat162float(ha);
    rb = b - __bfloat162float(hb);
    return ((uint32_t)__bfloat16_as_ushort(hb) << 16) | (uint32_t)__bfloat16_as_ushort(ha);
}
__device__ __forceinline__ uint32_t pack_lo(float a, float b) {
    return ((uint32_t)__bfloat16_as_ushort(__float2bfloat16(b)) << 16) |
           (uint32_t)__bfloat16_as_ushort(__float2bfloat16(a));
}

__device__ __forceinline__ void ldsm4(uint32_t* r, uint32_t addr) {
    asm volatile("ldmatrix.sync.aligned.m8n8.x4.shared.b16 {%0,%1,%2,%3}, [%4];"
                 : "=r"(r[0]), "=r"(r[1]), "=r"(r[2]), "=r"(r[3]) : "r"(addr));
}
__device__ __forceinline__ void mma_bf16(float* d, const uint32_t* a, const uint32_t* b) {
    asm volatile(
        "mma.sync.aligned.m16n8k16.row.col.f32.bf16.bf16.f32 "
        "{%0,%1,%2,%3}, {%4,%5,%6,%7}, {%8,%9}, {%0,%1,%2,%3};"
        : "+f"(d[0]), "+f"(d[1]), "+f"(d[2]), "+f"(d[3])
        : "r"(a[0]), "r"(a[1]), "r"(a[2]), "r"(a[3]), "r"(b[0]), "r"(b[1]));
}

extern __shared__ char esm[];

// ---------------- prep: P1 = x@Wmsg[0:64], P2 = x@Wmsg[64:128] ----------------
__global__ __launch_bounds__(256) void prep_k(const float* __restrict__ x,
                                              const float* __restrict__ Wmsg) {
    float* W_s = (float*)esm;
    float* xT  = (float*)(esm + 32768);
    int tx = threadIdx.x;
    for (int i = tx; i < 2048; i += 256)
        ((float4*)W_s)[i] = ((const float4*)Wmsg)[i];

    int es = tx >> 2, part = tx & 3;
    int node = blockIdx.x * 64 + es;
    int nc = node < NN ? node : NN - 1;
    const float4* xp = (const float4*)(x + (size_t)nc * 64) + part * 4;
    #pragma unroll
    for (int i = 0; i < 4; i++) {
        float4 v = xp[i];
        int kb = part * 16 + i * 4;
        xT[(kb + 0) * 64 + es] = v.x; xT[(kb + 1) * 64 + es] = v.y;
        xT[(kb + 2) * 64 + es] = v.z; xT[(kb + 3) * 64 + es] = v.w;
    }
    __syncthreads();

    int c0 = (tx & 15) * 4, e0 = (tx >> 4) * 4;
    float a1[4][4], a2[4][4];
    #pragma unroll
    for (int i = 0; i < 4; i++)
        #pragma unroll
        for (int j = 0; j < 4; j++) { a1[i][j] = 0.0f; a2[i][j] = 0.0f; }

    #pragma unroll 4
    for (int k = 0; k < 64; k++) {
        float4 f  = *(const float4*)(xT + k * 64 + e0);
        float4 w1 = *(const float4*)(W_s + k * 64 + c0);
        float4 w2 = *(const float4*)(W_s + (64 + k) * 64 + c0);
        a1[0][0] += f.x*w1.x; a1[0][1] += f.x*w1.y; a1[0][2] += f.x*w1.z; a1[0][3] += f.x*w1.w;
        a1[1][0] += f.y*w1.x; a1[1][1] += f.y*w1.y; a1[1][2] += f.y*w1.z; a1[1][3] += f.y*w1.w;
        a1[2][0] += f.z*w1.x; a1[2][1] += f.z*w1.y; a1[2][2] += f.z*w1.z; a1[2][3] += f.z*w1.w;
        a1[3][0] += f.w*w1.x; a1[3][1] += f.w*w1.y; a1[3][2] += f.w*w1.z; a1[3][3] += f.w*w1.w;
        a2[0][0] += f.x*w2.x; a2[0][1] += f.x*w2.y; a2[0][2] += f.x*w2.z; a2[0][3] += f.x*w2.w;
        a2[1][0] += f.y*w2.x; a2[1][1] += f.y*w2.y; a2[1][2] += f.y*w2.z; a2[1][3] += f.y*w2.w;
        a2[2][0] += f.z*w2.x; a2[2][1] += f.z*w2.y; a2[2][2] += f.z*w2.z; a2[2][3] += f.z*w2.w;
        a2[3][0] += f.w*w2.x; a2[3][1] += f.w*w2.y; a2[3][2] += f.w*w2.z; a2[3][3] += f.w*w2.w;
    }
    #pragma unroll
    for (int i = 0; i < 4; i++) {
        int n = blockIdx.x * 64 + e0 + i;
        if (n < NN) {
            *(float4*)(g_P1 + (size_t)n * 64 + c0) = make_float4(a1[i][0], a1[i][1], a1[i][2], a1[i][3]);
            *(float4*)(g_P2 + (size_t)n * 64 + c0) = make_float4(a2[i][0], a2[i][1], a2[i][2], a2[i][3]);
        }
    }
}

// ---------------- edge kernel: warp-independent slices + cp.async double buffer ----------------
#define ASTRIDE 272
#define O_B3   0                       // W3^T  [64n][hi128|lo128(+pad)]
#define O_BE   17408                   // We^T
#define O_A    34816                   // 8 warps x 2 bufs x 16 rows x 272B raw f32
#define O_SCAL 104448                  // 8 warps x 2 bufs x 320B (src16|dst16|rr32|di16)
#define O_WS   109568
#define O_BM   109824
#define O_BEB  110080
#define SMEM_EDGE 110336               // 2 CTAs/SM

__global__ __launch_bounds__(256, 2) void edge_k(
    const int* __restrict__ ei,
    const float* __restrict__ ea,
    const float* __restrict__ rr,
    const float* __restrict__ dinit,
    const float* __restrict__ Wmsg,
    const float* __restrict__ bmsg,
    const float* __restrict__ Wedge,
    const float* __restrict__ bedge,
    float* __restrict__ out)
{
    const int tx = threadIdx.x;
    const int wid = tx >> 5, lane = tx & 31;
    const uint32_t sb = smem_u32(esm);

    float* out_edge = out + (size_t)NN * 64;
    float* out_msg  = out + (size_t)NN * 64 + (size_t)NE * 64;
    float* out_str  = out + (size_t)NN * 64 + 2 * (size_t)NE * 64;

    // ---- one-time: stage W3^T, We^T as bf16 hi/lo ----
    for (int idx = tx; idx < 4096; idx += 256) {
        int n = idx >> 6, k = idx & 63;
        float w3 = Wmsg[(129 + k) * 64 + n];
        __nv_bfloat16 h = __float2bfloat16(w3);
        __nv_bfloat16 l = __float2bfloat16(w3 - __bfloat162float(h));
        *(__nv_bfloat16*)(esm + O_B3 + n * ASTRIDE + k * 2) = h;
        *(__nv_bfloat16*)(esm + O_B3 + n * ASTRIDE + 128 + k * 2) = l;
        float we = Wedge[k * 64 + n];
        h = __float2bfloat16(we);
        l = __float2bfloat16(we - __bfloat162float(h));
        *(__nv_bfloat16*)(esm + O_BE + n * ASTRIDE + k * 2) = h;
        *(__nv_bfloat16*)(esm + O_BE + n * ASTRIDE + 128 + k * 2) = l;
    }
    if (tx < 64) {
        ((float*)(esm + O_WS))[tx]  = Wmsg[128 * 64 + tx];
        ((float*)(esm + O_BM))[tx]  = bmsg[tx];
        ((float*)(esm + O_BEB))[tx] = bedge[tx];
    }
    __syncthreads();   // only block-wide sync

    // B fragment geometry
    const int q = lane >> 3, r = lane & 7;
    uint32_t b3c[4], bec[4];
    #pragma unroll
    for (int c = 0; c < 4; c++) {
        uint32_t brow = (uint32_t)(c * 16 + r + (q >> 1) * 8);
        b3c[c] = sb + O_B3 + brow * ASTRIDE + (q & 1) * 16;
        bec[c] = sb + O_BE + brow * ASTRIDE + (q & 1) * 16;
    }

    const int tg = lane >> 2;          // A fragment row group
    const int ci = lane & 3;           // A fragment k pair
    const int tc = ci * 2;
    const bool evenlane = (lane & 1) == 0;

    const uint32_t Abuf  = sb + O_A + (uint32_t)wid * 8704;      // + p*4352
    const uint32_t Sbuf  = sb + O_SCAL + (uint32_t)wid * 640;    // + p*320
    const char* Abase = esm + O_A + wid * 8704;
    const char* Sbase = esm + O_SCAL + wid * 640;

    const float* ws_s = (const float*)(esm + O_WS);
    const float* bm_s = (const float*)(esm + O_BM);
    const float* beb  = (const float*)(esm + O_BEB);

    // cp.async issue for one slice into buffer par (all 32 lanes)
    const int rowl = lane >> 1, chalf = (lane & 1) * 32;
    auto issue = [&](int sl, int par) {
        uint32_t ad = Abuf + par * 4352 + rowl * ASTRIDE + chalf * 4;
        const float* as = ea + (size_t)sl * 16 * 64 + rowl * 64 + chalf;
        #pragma unroll
        for (int i = 0; i < 8; i++) cp16(ad + i * 16, as + i * 4);
        uint32_t sd = Sbuf + par * 320;
        if (lane < 4)       cp16(sd + lane * 16,             ei + (size_t)sl * 16 + lane * 4);
        else if (lane < 8)  cp16(sd + 64 + (lane - 4) * 16,  ei + NE + (size_t)sl * 16 + (lane - 4) * 4);
        else if (lane < 16) cp16(sd + 128 + (lane - 8) * 16, rr + (size_t)sl * 32 + (lane - 8) * 4);
        else if (lane < 20) cp16(sd + 256 + (lane - 16) * 16, dinit + (size_t)sl * 16 + (lane - 16) * 4);
    };

    const int nwarps = gridDim.x * 8;
    int slice = blockIdx.x * 8 + wid;
    if (slice < NSLICE) issue(slice, 0);
    CP_COMMIT();

    int p = 0;
    for (; slice < NSLICE; slice += nwarps, p ^= 1) {
        __syncwarp();   // all lanes done reading buf p^1 from previous iteration
        int nxt = slice + nwarps;
        if (nxt < NSLICE) issue(nxt, p ^ 1);
        CP_COMMIT();
        CP_WAIT1();     // buf p complete (this thread)
        __syncwarp();   // cross-lane visibility of buf p

        const char* Ap = Abase + p * 4352;
        const int*   s_src = (const int*)(Sbase + p * 320);
        const int*   s_dst = s_src + 16;
        const float* s_rr  = (const float*)(s_dst + 16);
        const float* s_di  = s_rr + 32;

        // strain + count + out_str (lane<16)
        if (lane < 16) {
            float r0 = s_rr[2 * lane], r1 = s_rr[2 * lane + 1];
            float di = s_di[lane];
            float s = (sqrtf(r0 * r0 + r1 * r1) - di) / di;
            out_str[(size_t)slice * 16 + lane] = s;
            atomicAdd(&g_cnt[s_dst[lane]], 1.0f);
        }

        // ---- GEMM1: A frags built from raw f32 smem (LDS+pack), B via ldsm ----
        float acc[8][4];
        #pragma unroll
        for (int i = 0; i < 8; i++)
            #pragma unroll
            for (int j = 0; j < 4; j++) acc[i][j] = 0.0f;

        #pragma unroll
        for (int st = 0; st < 4; st++) {
            int koff = (st * 16 + tc) * 4;
            const char* rA = Ap + tg * ASTRIDE;
            const char* rB = Ap + (tg + 8) * ASTRIDE;
            float2 f0 = *(const float2*)(rA + koff);
            float2 f1 = *(const float2*)(rB + koff);
            float2 f2 = *(const float2*)(rA + koff + 32);
            float2 f3 = *(const float2*)(rB + koff + 32);
            uint32_t ah[4], al[4];
            float rx, ry;
            ah[0] = pack_hi(f0.x, f0.y, rx, ry); al[0] = pack_lo(rx, ry);
            ah[1] = pack_hi(f1.x, f1.y, rx, ry); al[1] = pack_lo(rx, ry);
            ah[2] = pack_hi(f2.x, f2.y, rx, ry); al[2] = pack_lo(rx, ry);
            ah[3] = pack_hi(f3.x, f3.y, rx, ry); al[3] = pack_lo(rx, ry);
            #pragma unroll
            for (int c = 0; c < 4; c++) {
                uint32_t bh[4], bl[4];
                ldsm4(bh, b3c[c] + st * 32);
                ldsm4(bl, b3c[c] + 128 + st * 32);
                mma_bf16(acc[2 * c],     ah, bh);   mma_bf16(acc[2 * c + 1], ah, bh + 2);
                mma_bf16(acc[2 * c],     al, bh);   mma_bf16(acc[2 * c + 1], al, bh + 2);
                mma_bf16(acc[2 * c],     ah, bl);   mma_bf16(acc[2 * c + 1], ah, bl + 2);
            }
        }

        // ---- epilogue 1: msg = softplus(acc + P1[src] + P2[dst] + s*ws + bm) ----
        uint32_t mh[16], ml[16];
        #pragma unroll
        for (int half = 0; half < 2; half++) {
            int rl = tg + half * 8;
            size_t e = (size_t)slice * 16 + rl;
            int src = s_src[rl];
            int dst = s_dst[rl];
            float r0 = s_rr[2 * rl], r1 = s_rr[2 * rl + 1];
            float di = s_di[rl];
            float s = (sqrtf(r0 * r0 + r1 * r1) - di) / di;
            const float* p1r = g_P1 + (size_t)src * 64;
            const float* p2r = g_P2 + (size_t)dst * 64;
            float* ap = g_agg + (size_t)dst * 64;
            #pragma unroll
            for (int nf = 0; nf < 8; nf++) {
                int n = nf * 8 + tc;
                float2 p1 = *(const float2*)(p1r + n);
                float2 p2 = *(const float2*)(p2r + n);
                float m0 = softplus_f(acc[nf][half * 2 + 0] + p1.x + p2.x + s * ws_s[n]     + bm_s[n]);
                float m1 = softplus_f(acc[nf][half * 2 + 1] + p1.y + p2.y + s * ws_s[n + 1] + bm_s[n + 1]);
                float q0, q1;
                mh[half * 8 + nf] = pack_hi(m0, m1, q0, q1);
                ml[half * 8 + nf] = pack_lo(q0, q1);
                float o0 = __shfl_xor_sync(0xFFFFFFFFu, m0, 1);
                float o1 = __shfl_xor_sync(0xFFFFFFFFu, m1, 1);
                if (evenlane) {
                    *(float4*)(out_msg + e * 64 + n) = make_float4(m0, m1, o0, o1);
                    red_add_v4(ap + n, m0, m1, o0, o1);
                }
            }
        }

        // ---- GEMM2: edge_new = msg @ Wedge; A-frags straight from mh/ml ----
        float a2[8][4];
        #pragma unroll
        for (int i = 0; i < 8; i++)
            #pragma unroll
            for (int j = 0; j < 4; j++) a2[i][j] = 0.0f;

        #pragma unroll
        for (int st = 0; st < 4; st++) {
            uint32_t ah[4] = { mh[2 * st], mh[8 + 2 * st], mh[2 * st + 1], mh[8 + 2 * st + 1] };
            uint32_t al[4] = { ml[2 * st], ml[8 + 2 * st], ml[2 * st + 1], ml[8 + 2 * st + 1] };
            #pragma unroll
            for (int c = 0; c < 4; c++) {
                uint32_t bh[4], bl[4];
                ldsm4(bh, bec[c] + st * 32);
                ldsm4(bl, bec[c] + 128 + st * 32);
                mma_bf16(a2[2 * c],     ah, bh);   mma_bf16(a2[2 * c + 1], ah, bh + 2);
                mma_bf16(a2[2 * c],     al, bh);   mma_bf16(a2[2 * c + 1], al, bh + 2);
                mma_bf16(a2[2 * c],     ah, bl);   mma_bf16(a2[2 * c + 1], ah, bl + 2);
            }
        }
        #pragma unroll
        for (int half = 0; half < 2; half++) {
            size_t e = (size_t)slice * 16 + tg + half * 8;
            #pragma unroll
            for (int nf = 0; nf < 8; nf++) {
                int n = nf * 8 + tc;
                float v0 = a2[nf][half * 2 + 0] + beb[n];
                float v1 = a2[nf][half * 2 + 1] + beb[n + 1];
                float o0 = __shfl_xor_sync(0xFFFFFFFFu, v0, 1);
                float o1 = __shfl_xor_sync(0xFFFFFFFFu, v1, 1);
                if (evenlane)
                    *(float4*)(out_edge + e * 64 + n) = make_float4(v0, v1, o0, o1);
            }
        }
    }
}

// ---------------- node update ----------------
__global__ __launch_bounds__(256) void node_k(
    const float* __restrict__ x,
    const float* __restrict__ Wupd,
    const float* __restrict__ bupd,
    float* __restrict__ out_x)
{
    float* W_s = (float*)esm;
    float* fT  = (float*)(esm + 32768);
    int tx = threadIdx.x;
    for (int i = tx; i < 2048; i += 256)
        ((float4*)W_s)[i] = ((const float4*)Wupd)[i];

    int es = tx >> 2, part = tx & 3;
    int node = blockIdx.x * 64 + es;
    int nc = node < NN ? node : NN - 1;
    float inv = 1.0f / fmaxf(g_cnt[nc], 1.0f);
    const float4* xp = (const float4*)(x + (size_t)nc * 64) + part * 4;
    const float4* ap = (const float4*)(g_agg + (size_t)nc * 64) + part * 4;
    #pragma unroll
    for (int i = 0; i < 4; i++) {
        float4 v = xp[i];
        int kb = part * 16 + i * 4;
        fT[(kb + 0) * 64 + es] = v.x; fT[(kb + 1) * 64 + es] = v.y;
        fT[(kb + 2) * 64 + es] = v.z; fT[(kb + 3) * 64 + es] = v.w;
        float4 w = ap[i];
        fT[(64 + kb + 0) * 64 + es] = w.x * inv; fT[(64 + kb + 1) * 64 + es] = w.y * inv;
        fT[(64 + kb + 2) * 64 + es] = w.z * inv; fT[(64 + kb + 3) * 64 + es] = w.w * inv;
    }
    __syncthreads();

    int c0 = (tx & 15) * 4, e0 = (tx >> 4) * 4;
    float acc[4][4];
    #pragma unroll
    for (int i = 0; i < 4; i++)
        #pragma unroll
        for (int j = 0; j < 4; j++) acc[i][j] = 0.0f;

    #pragma unroll 8
    for (int k = 0; k < 128; k++) {
        float4 f = *(const float4*)(fT + k * 64 + e0);
        float4 w = *(const float4*)(W_s + k * 64 + c0);
        acc[0][0] += f.x*w.x; acc[0][1] += f.x*w.y; acc[0][2] += f.x*w.z; acc[0][3] += f.x*w.w;
        acc[1][0] += f.y*w.x; acc[1][1] += f.y*w.y; acc[1][2] += f.y*w.z; acc[1][3] += f.y*w.w;
        acc[2][0] += f.z*w.x; acc[2][1] += f.z*w.y; acc[2][2] += f.z*w.z; acc[2][3] += f.z*w.w;
        acc[3][0] += f.w*w.x; acc[3][1] += f.w*w.y; acc[3][2] += f.w*w.z; acc[3][3] += f.w*w.w;
    }
    float4 b = *(const float4*)(bupd + c0);
    #pragma unroll
    for (int i = 0; i < 4; i++) {
        int n = blockIdx.x * 64 + e0 + i;
        if (n < NN)
            *(float4*)(out_x + (size_t)n * 64 + c0) =
                make_float4(acc[i][0] + b.x, acc[i][1] + b.y, acc[i][2] + b.z, acc[i][3] + b.w);
    }
}

extern "C" void kernel_launch(void* const* d_in, const int* in_sizes, int n_in,
                              void* d_out, int out_size) {
    const float* x     = (const float*)d_in[0];
    const int*   ei    = (const int*)d_in[1];
    const float* ea    = (const float*)d_in[2];
    const float* rr    = (const float*)d_in[3];
    const float* dinit = (const float*)d_in[4];
    const float* Wmsg  = (const float*)d_in[5];
    const float* bmsg  = (const float*)d_in[6];
    const float* Wupd  = (const float*)d_in[7];
    const float* bupd  = (const float*)d_in[8];
    const float* Wedge = (const float*)d_in[9];
    const float* bedge = (const float*)d_in[10];
    float* out = (float*)d_out;
    (void)in_sizes; (void)n_in; (void)out_size;

    cudaFuncSetAttribute(edge_k, cudaFuncAttributeMaxDynamicSharedMemorySize, SMEM_EDGE);
    cudaFuncSetAttribute(node_k, cudaFuncAttributeMaxDynamicSharedMemorySize, 65536);
    cudaFuncSetAttribute(prep_k, cudaFuncAttributeMaxDynamicSharedMemorySize, 49152);

    zero_k<<<512, 256>>>();
    prep_k<<<(NN + 63) / 64, 256, 49152>>>(x, Wmsg);
    noop_k<<<1, 32>>>();   // keeps edge_k in the ncu capture slot (launch idx 3)
    edge_k<<<296, 256, SMEM_EDGE>>>(ei, ea, rr, dinit, Wmsg, bmsg, Wedge, bedge, out);
    node_k<<<(NN + 63) / 64, 256, 65536>>>(x, Wupd, bupd, out);
}

// round 15
// speedup vs baseline: 1.0031x; 1.0031x over previous
#include <cuda_runtime.h>
#include <cuda_bf16.h>
#include <math.h>
#include <stdint.h>

#define NN 50000
#define NE 800000
#define NSLICE (NE / 16)   // 50000 16-edge warp-slices

// ---------------- scratch (static device globals, no allocation) ----------------
__device__ float g_agg[(size_t)NN * 64];
__device__ float g_cnt[NN];
__device__ float g_P1[(size_t)NN * 64];
__device__ float g_P2[(size_t)NN * 64];

__global__ void zero_k() {
    int i = blockIdx.x * blockDim.x + threadIdx.x;
    int stride = gridDim.x * blockDim.x;
    for (int j = i; j < NN * 64; j += stride) g_agg[j] = 0.0f;
    for (int j = i; j < NN; j += stride) g_cnt[j] = 0.0f;
}

// no-op: keeps edge_k in the ncu-captured launch slot (absolute idx 3)
__global__ void noop_k() {}

// MUFU-free softplus: all FFMA/ALU, rel err ~1.5e-6.
__device__ __forceinline__ float softplus_f(float v) {
    float w = -fabsf(v);
    float t = fmaxf(w * 1.4426950408889634f, -120.0f);
    float nf = rintf(t);
    float f = t - nf;
    float g = f * 0.6931471805599453f;
    float p = 1.388888889e-3f;
    p = p * g + 8.333333333e-3f;
    p = p * g + 4.166666667e-2f;
    p = p * g + 1.666666667e-1f;
    p = p * g + 0.5f;
    p = p * g + 1.0f;
    p = p * g + 1.0f;
    int ni = __float2int_rn(nf);
    float scale = __int_as_float((127 + ni) << 23);
    float u = p * scale;
    float d = 2.0f + u;
    float y = 0.8249f - 0.16666667f * d;
    y = y * (2.0f - d * y);
    y = y * (2.0f - d * y);
    float z = u * y;
    float z2 = z * z;
    float q = 0.11111111f;
    q = q * z2 + 0.14285714f;
    q = q * z2 + 0.2f;
    q = q * z2 + 0.33333333f;
    q = q * z2 + 1.0f;
    float lg = 2.0f * z * q;
    return fmaxf(v, 0.0f) + lg;
}

__device__ __forceinline__ uint32_t smem_u32(const void* p) {
    uint32_t a;
    asm("{ .reg .u64 t; cvta.to.shared.u64 t, %1; cvt.u32.u64 %0, t; }" : "=r"(a) : "l"(p));
    return a;
}

__device__ __forceinline__ void red_add_v4(float* addr, float a, float b, float c, float d) {
    asm volatile("red.global.add.v4.f32 [%0], {%1, %2, %3, %4};"
                 :: "l"(addr), "f"(a), "f"(b), "f"(c), "f"(d) : "memory");
}

__device__ __forceinline__ void cp16(uint32_t dst, const void* src) {
    asm volatile("cp.async.cg.shared.global [%0], [%1], 16;" :: "r"(dst), "l"(src) : "memory");
}
#define CP_COMMIT() asm volatile("cp.async.commit_group;" ::: "memory")
#define CP_WAIT1()  asm volatile("cp.async.wait_group 1;" ::: "memory")

__device__ __forceinline__ uint32_t pack_hi(float a, float b, float& ra, float& rb) {
    __nv_bfloat16 ha = __float2bfloat16(a);
    __nv_bfloat16 hb = __float2bfloat16(b);
    ra = a - __bfloat162float(ha);
    rb = b - __bfloat162float(hb);
    return ((uint32_t)__bfloat16_as_ushort(hb) << 16) | (uint32_t)__bfloat16_as_ushort(ha);
}
__device__ __forceinline__ uint32_t pack_lo(float a, float b) {
    return ((uint32_t)__bfloat16_as_ushort(__float2bfloat16(b)) << 16) |
           (uint32_t)__bfloat16_as_ushort(__float2bfloat16(a));
}

__device__ __forceinline__ void ldsm4(uint32_t* r, uint32_t addr) {
    asm volatile("ldmatrix.sync.aligned.m8n8.x4.shared.b16 {%0,%1,%2,%3}, [%4];"
                 : "=r"(r[0]), "=r"(r[1]), "=r"(r[2]), "=r"(r[3]) : "r"(addr));
}
__device__ __forceinline__ void mma_bf16(float* d, const uint32_t* a, const uint32_t* b) {
    asm volatile(
        "mma.sync.aligned.m16n8k16.row.col.f32.bf16.bf16.f32 "
        "{%0,%1,%2,%3}, {%4,%5,%6,%7}, {%8,%9}, {%0,%1,%2,%3};"
        : "+f"(d[0]), "+f"(d[1]), "+f"(d[2]), "+f"(d[3])
        : "r"(a[0]), "r"(a[1]), "r"(a[2]), "r"(a[3]), "r"(b[0]), "r"(b[1]));
}

extern __shared__ char esm[];

// ---------------- prep: P1 = x@Wmsg[0:64], P2 = x@Wmsg[64:128] ----------------
__global__ __launch_bounds__(256) void prep_k(const float* __restrict__ x,
                                              const float* __restrict__ Wmsg) {
    float* W_s = (float*)esm;
    float* xT  = (float*)(esm + 32768);
    int tx = threadIdx.x;
    for (int i = tx; i < 2048; i += 256)
        ((float4*)W_s)[i] = ((const float4*)Wmsg)[i];

    int es = tx >> 2, part = tx & 3;
    int node = blockIdx.x * 64 + es;
    int nc = node < NN ? node : NN - 1;
    const float4* xp = (const float4*)(x + (size_t)nc * 64) + part * 4;
    #pragma unroll
    for (int i = 0; i < 4; i++) {
        float4 v = xp[i];
        int kb = part * 16 + i * 4;
        xT[(kb + 0) * 64 + es] = v.x; xT[(kb + 1) * 64 + es] = v.y;
        xT[(kb + 2) * 64 + es] = v.z; xT[(kb + 3) * 64 + es] = v.w;
    }
    __syncthreads();

    int c0 = (tx & 15) * 4, e0 = (tx >> 4) * 4;
    float a1[4][4], a2[4][4];
    #pragma unroll
    for (int i = 0; i < 4; i++)
        #pragma unroll
        for (int j = 0; j < 4; j++) { a1[i][j] = 0.0f; a2[i][j] = 0.0f; }

    #pragma unroll 4
    for (int k = 0; k < 64; k++) {
        float4 f  = *(const float4*)(xT + k * 64 + e0);
        float4 w1 = *(const float4*)(W_s + k * 64 + c0);
        float4 w2 = *(const float4*)(W_s + (64 + k) * 64 + c0);
        a1[0][0] += f.x*w1.x; a1[0][1] += f.x*w1.y; a1[0][2] += f.x*w1.z; a1[0][3] += f.x*w1.w;
        a1[1][0] += f.y*w1.x; a1[1][1] += f.y*w1.y; a1[1][2] += f.y*w1.z; a1[1][3] += f.y*w1.w;
        a1[2][0] += f.z*w1.x; a1[2][1] += f.z*w1.y; a1[2][2] += f.z*w1.z; a1[2][3] += f.z*w1.w;
        a1[3][0] += f.w*w1.x; a1[3][1] += f.w*w1.y; a1[3][2] += f.w*w1.z; a1[3][3] += f.w*w1.w;
        a2[0][0] += f.x*w2.x; a2[0][1] += f.x*w2.y; a2[0][2] += f.x*w2.z; a2[0][3] += f.x*w2.w;
        a2[1][0] += f.y*w2.x; a2[1][1] += f.y*w2.y; a2[1][2] += f.y*w2.z; a2[1][3] += f.y*w2.w;
        a2[2][0] += f.z*w2.x; a2[2][1] += f.z*w2.y; a2[2][2] += f.z*w2.z; a2[2][3] += f.z*w2.w;
        a2[3][0] += f.w*w2.x; a2[3][1] += f.w*w2.y; a2[3][2] += f.w*w2.z; a2[3][3] += f.w*w2.w;
    }
    #pragma unroll
    for (int i = 0; i < 4; i++) {
        int n = blockIdx.x * 64 + e0 + i;
        if (n < NN) {
            *(float4*)(g_P1 + (size_t)n * 64 + c0) = make_float4(a1[i][0], a1[i][1], a1[i][2], a1[i][3]);
            *(float4*)(g_P2 + (size_t)n * 64 + c0) = make_float4(a2[i][0], a2[i][1], a2[i][2], a2[i][3]);
        }
    }
}

// ---------------- edge kernel: warp-independent slices + cp.async double buffer ----------------
#define ASTRIDE 272
#define O_B3   0                       // W3^T  [64n][hi128|lo128(+pad)]
#define O_BE   17408                   // We^T
#define O_A    34816                   // 8 warps x 2 bufs x 16 rows x 272B raw f32
#define O_SCAL 104448                  // 8 warps x 2 bufs x 320B (src16|dst16|rr32|di16)
#define O_WS   109568
#define O_BM   109824
#define O_BEB  110080
#define SMEM_EDGE 110336               // 2 CTAs/SM

__global__ __launch_bounds__(256, 2) void edge_k(
    const int* __restrict__ ei,
    const float* __restrict__ ea,
    const float* __restrict__ rr,
    const float* __restrict__ dinit,
    const float* __restrict__ Wmsg,
    const float* __restrict__ bmsg,
    const float* __restrict__ Wedge,
    const float* __restrict__ bedge,
    float* __restrict__ out)
{
    const int tx = threadIdx.x;
    const int wid = tx >> 5, lane = tx & 31;
    const uint32_t sb = smem_u32(esm);

    float* out_edge = out + (size_t)NN * 64;
    float* out_msg  = out + (size_t)NN * 64 + (size_t)NE * 64;
    float* out_str  = out + (size_t)NN * 64 + 2 * (size_t)NE * 64;

    // ---- one-time: stage W3^T, We^T as bf16 hi/lo ----
    for (int idx = tx; idx < 4096; idx += 256) {
        int n = idx >> 6, k = idx & 63;
        float w3 = Wmsg[(129 + k) * 64 + n];
        __nv_bfloat16 h = __float2bfloat16(w3);
        __nv_bfloat16 l = __float2bfloat16(w3 - __bfloat162float(h));
        *(__nv_bfloat16*)(esm + O_B3 + n * ASTRIDE + k * 2) = h;
        *(__nv_bfloat16*)(esm + O_B3 + n * ASTRIDE + 128 + k * 2) = l;
        float we = Wedge[k * 64 + n];
        h = __float2bfloat16(we);
        l = __float2bfloat16(we - __bfloat162float(h));
        *(__nv_bfloat16*)(esm + O_BE + n * ASTRIDE + k * 2) = h;
        *(__nv_bfloat16*)(esm + O_BE + n * ASTRIDE + 128 + k * 2) = l;
    }
    if (tx < 64) {
        ((float*)(esm + O_WS))[tx]  = Wmsg[128 * 64 + tx];
        ((float*)(esm + O_BM))[tx]  = bmsg[tx];
        ((float*)(esm + O_BEB))[tx] = bedge[tx];
    }
    __syncthreads();   // only block-wide sync

    // B fragment geometry
    const int q = lane >> 3, r = lane & 7;
    uint32_t b3c[4], bec[4];
    #pragma unroll
    for (int c = 0; c < 4; c++) {
        uint32_t brow = (uint32_t)(c * 16 + r + (q >> 1) * 8);
        b3c[c] = sb + O_B3 + brow * ASTRIDE + (q & 1) * 16;
        bec[c] = sb + O_BE + brow * ASTRIDE + (q & 1) * 16;
    }

    const int tg = lane >> 2;          // A fragment row group
    const int ci = lane & 3;           // A fragment k pair
    const int tc = ci * 2;
    const bool evenlane = (lane & 1) == 0;

    const uint32_t Abuf  = sb + O_A + (uint32_t)wid * 8704;      // + p*4352
    const uint32_t Sbuf  = sb + O_SCAL + (uint32_t)wid * 640;    // + p*320
    const char* Abase = esm + O_A + wid * 8704;
    const char* Sbase = esm + O_SCAL + wid * 640;

    const float* ws_s = (const float*)(esm + O_WS);
    const float* bm_s = (const float*)(esm + O_BM);
    const float* beb  = (const float*)(esm + O_BEB);

    // cp.async issue for one slice into buffer par (all 32 lanes)
    const int rowl = lane >> 1, chalf = (lane & 1) * 32;
    auto issue = [&](int sl, int par) {
        uint32_t ad = Abuf + par * 4352 + rowl * ASTRIDE + chalf * 4;
        const float* as = ea + (size_t)sl * 16 * 64 + rowl * 64 + chalf;
        #pragma unroll
        for (int i = 0; i < 8; i++) cp16(ad + i * 16, as + i * 4);
        uint32_t sd = Sbuf + par * 320;
        if (lane < 4)       cp16(sd + lane * 16,             ei + (size_t)sl * 16 + lane * 4);
        else if (lane < 8)  cp16(sd + 64 + (lane - 4) * 16,  ei + NE + (size_t)sl * 16 + (lane - 4) * 4);
        else if (lane < 16) cp16(sd + 128 + (lane - 8) * 16, rr + (size_t)sl * 32 + (lane - 8) * 4);
        else if (lane < 20) cp16(sd + 256 + (lane - 16) * 16, dinit + (size_t)sl * 16 + (lane - 16) * 4);
    };

    const int nwarps = gridDim.x * 8;
    int slice = blockIdx.x * 8 + wid;
    if (slice < NSLICE) issue(slice, 0);
    CP_COMMIT();

    int p = 0;
    for (; slice < NSLICE; slice += nwarps, p ^= 1) {
        __syncwarp();   // all lanes done reading buf p^1 from previous iteration
        int nxt = slice + nwarps;
        if (nxt < NSLICE) issue(nxt, p ^ 1);
        CP_COMMIT();
        CP_WAIT1();     // buf p complete (this thread)
        __syncwarp();   // cross-lane visibility of buf p

        const char* Ap = Abase + p * 4352;
        const int*   s_src = (const int*)(Sbase + p * 320);
        const int*   s_dst = s_src + 16;
        const float* s_rr  = (const float*)(s_dst + 16);
        const float* s_di  = s_rr + 32;

        // strain + count + out_str (lane<16)
        if (lane < 16) {
            float r0 = s_rr[2 * lane], r1 = s_rr[2 * lane + 1];
            float di = s_di[lane];
            float s = (sqrtf(r0 * r0 + r1 * r1) - di) / di;
            out_str[(size_t)slice * 16 + lane] = s;
            atomicAdd(&g_cnt[s_dst[lane]], 1.0f);
        }

        // ---- GEMM1: A frags built from raw f32 smem (LDS+pack), B via ldsm ----
        float acc[8][4];
        #pragma unroll
        for (int i = 0; i < 8; i++)
            #pragma unroll
            for (int j = 0; j < 4; j++) acc[i][j] = 0.0f;

        #pragma unroll
        for (int st = 0; st < 4; st++) {
            int koff = (st * 16 + tc) * 4;
            const char* rA = Ap + tg * ASTRIDE;
            const char* rB = Ap + (tg + 8) * ASTRIDE;
            float2 f0 = *(const float2*)(rA + koff);
            float2 f1 = *(const float2*)(rB + koff);
            float2 f2 = *(const float2*)(rA + koff + 32);
            float2 f3 = *(const float2*)(rB + koff + 32);
            uint32_t ah[4], al[4];
            float rx, ry;
            ah[0] = pack_hi(f0.x, f0.y, rx, ry); al[0] = pack_lo(rx, ry);
            ah[1] = pack_hi(f1.x, f1.y, rx, ry); al[1] = pack_lo(rx, ry);
            ah[2] = pack_hi(f2.x, f2.y, rx, ry); al[2] = pack_lo(rx, ry);
            ah[3] = pack_hi(f3.x, f3.y, rx, ry); al[3] = pack_lo(rx, ry);
            #pragma unroll
            for (int c = 0; c < 4; c++) {
                uint32_t bh[4], bl[4];
                ldsm4(bh, b3c[c] + st * 32);
                ldsm4(bl, b3c[c] + 128 + st * 32);
                mma_bf16(acc[2 * c],     ah, bh);   mma_bf16(acc[2 * c + 1], ah, bh + 2);
                mma_bf16(acc[2 * c],     al, bh);   mma_bf16(acc[2 * c + 1], al, bh + 2);
                mma_bf16(acc[2 * c],     ah, bl);   mma_bf16(acc[2 * c + 1], ah, bl + 2);
            }
        }

        // ---- epilogue 1: msg = softplus(acc + P1[src] + P2[dst] + s*ws + bm) ----
        uint32_t mh[16], ml[16];
        #pragma unroll
        for (int half = 0; half < 2; half++) {
            int rl = tg + half * 8;
            size_t e = (size_t)slice * 16 + rl;
            int src = s_src[rl];
            int dst = s_dst[rl];
            float r0 = s_rr[2 * rl], r1 = s_rr[2 * rl + 1];
            float di = s_di[rl];
            float s = (sqrtf(r0 * r0 + r1 * r1) - di) / di;
            const float* p1r = g_P1 + (size_t)src * 64;
            const float* p2r = g_P2 + (size_t)dst * 64;
            float* ap = g_agg + (size_t)dst * 64;
            #pragma unroll
            for (int nf = 0; nf < 8; nf++) {
                int n = nf * 8 + tc;
                float2 p1 = *(const float2*)(p1r + n);
                float2 p2 = *(const float2*)(p2r + n);
                float m0 = softplus_f(acc[nf][half * 2 + 0] + p1.x + p2.x + s * ws_s[n]     + bm_s[n]);
                float m1 = softplus_f(acc[nf][half * 2 + 1] + p1.y + p2.y + s * ws_s[n + 1] + bm_s[n + 1]);
                float q0, q1;
                mh[half * 8 + nf] = pack_hi(m0, m1, q0, q1);
                ml[half * 8 + nf] = pack_lo(q0, q1);
                float o0 = __shfl_xor_sync(0xFFFFFFFFu, m0, 1);
                float o1 = __shfl_xor_sync(0xFFFFFFFFu, m1, 1);
                if (evenlane) {
                    *(float4*)(out_msg + e * 64 + n) = make_float4(m0, m1, o0, o1);
                    red_add_v4(ap + n, m0, m1, o0, o1);
                }
            }
        }

        // ---- GEMM2: edge_new = msg @ Wedge; A-frags straight from mh/ml ----
        float a2[8][4];
        #pragma unroll
        for (int i = 0; i < 8; i++)
            #pragma unroll
            for (int j = 0; j < 4; j++) a2[i][j] = 0.0f;

        #pragma unroll
        for (int st = 0; st < 4; st++) {
            uint32_t ah[4] = { mh[2 * st], mh[8 + 2 * st], mh[2 * st + 1], mh[8 + 2 * st + 1] };
            uint32_t al[4] = { ml[2 * st], ml[8 + 2 * st], ml[2 * st + 1], ml[8 + 2 * st + 1] };
            #pragma unroll
            for (int c = 0; c < 4; c++) {
                uint32_t bh[4], bl[4];
                ldsm4(bh, bec[c] + st * 32);
                ldsm4(bl, bec[c] + 128 + st * 32);
                mma_bf16(a2[2 * c],     ah, bh);   mma_bf16(a2[2 * c + 1], ah, bh + 2);
                mma_bf16(a2[2 * c],     al, bh);   mma_bf16(a2[2 * c + 1], al, bh + 2);
                mma_bf16(a2[2 * c],     ah, bl);   mma_bf16(a2[2 * c + 1], ah, bl + 2);
            }
        }
        #pragma unroll
        for (int half = 0; half < 2; half++) {
            size_t e = (size_t)slice * 16 + tg + half * 8;
            #pragma unroll
            for (int nf = 0; nf < 8; nf++) {
                int n = nf * 8 + tc;
                float v0 = a2[nf][half * 2 + 0] + beb[n];
                float v1 = a2[nf][half * 2 + 1] + beb[n + 1];
                float o0 = __shfl_xor_sync(0xFFFFFFFFu, v0, 1);
                float o1 = __shfl_xor_sync(0xFFFFFFFFu, v1, 1);
                if (evenlane)
                    *(float4*)(out_edge + e * 64 + n) = make_float4(v0, v1, o0, o1);
            }
        }
    }
}

// ---------------- node update ----------------
__global__ __launch_bounds__(256) void node_k(
    const float* __restrict__ x,
    const float* __restrict__ Wupd,
    const float* __restrict__ bupd,
    float* __restrict__ out_x)
{
    float* W_s = (float*)esm;
    float* fT  = (float*)(esm + 32768);
    int tx = threadIdx.x;
    for (int i = tx; i < 2048; i += 256)
        ((float4*)W_s)[i] = ((const float4*)Wupd)[i];

    int es = tx >> 2, part = tx & 3;
    int node = blockIdx.x * 64 + es;
    int nc = node < NN ? node : NN - 1;
    float inv = 1.0f / fmaxf(g_cnt[nc], 1.0f);
    const float4* xp = (const float4*)(x + (size_t)nc * 64) + part * 4;
    const float4* ap = (const float4*)(g_agg + (size_t)nc * 64) + part * 4;
    #pragma unroll
    for (int i = 0; i < 4; i++) {
        float4 v = xp[i];
        int kb = part * 16 + i * 4;
        fT[(kb + 0) * 64 + es] = v.x; fT[(kb + 1) * 64 + es] = v.y;
        fT[(kb + 2) * 64 + es] = v.z; fT[(kb + 3) * 64 + es] = v.w;
        float4 w = ap[i];
        fT[(64 + kb + 0) * 64 + es] = w.x * inv; fT[(64 + kb + 1) * 64 + es] = w.y * inv;
        fT[(64 + kb + 2) * 64 + es] = w.z * inv; fT[(64 + kb + 3) * 64 + es] = w.w * inv;
    }
    __syncthreads();

    int c0 = (tx & 15) * 4, e0 = (tx >> 4) * 4;
    float acc[4][4];
    #pragma unroll
    for (int i = 0; i < 4; i++)
        #pragma unroll
        for (int j = 0; j < 4; j++) acc[i][j] = 0.0f;

    #pragma unroll 8
    for (int k = 0; k < 128; k++) {
        float4 f = *(const float4*)(fT + k * 64 + e0);
        float4 w = *(const float4*)(W_s + k * 64 + c0);
        acc[0][0] += f.x*w.x; acc[0][1] += f.x*w.y; acc[0][2] += f.x*w.z; acc[0][3] += f.x*w.w;
        acc[1][0] += f.y*w.x; acc[1][1] += f.y*w.y; acc[1][2] += f.y*w.z; acc[1][3] += f.y*w.w;
        acc[2][0] += f.z*w.x; acc[2][1] += f.z*w.y; acc[2][2] += f.z*w.z; acc[2][3] += f.z*w.w;
        acc[3][0] += f.w*w.x; acc[3][1] += f.w*w.y; acc[3][2] += f.w*w.z; acc[3][3] += f.w*w.w;
    }
    float4 b = *(const float4*)(bupd + c0);
    #pragma unroll
    for (int i = 0; i < 4; i++) {
        int n = blockIdx.x * 64 + e0 + i;
        if (n < NN)
            *(float4*)(out_x + (size_t)n * 64 + c0) =
                make_float4(acc[i][0] + b.x, acc[i][1] + b.y, acc[i][2] + b.z, acc[i][3] + b.w);
    }
}

extern "C" void kernel_launch(void* const* d_in, const int* in_sizes, int n_in,
                              void* d_out, int out_size) {
    const float* x     = (const float*)d_in[0];
    const int*   ei    = (const int*)d_in[1];
    const float* ea    = (const float*)d_in[2];
    const float* rr    = (const float*)d_in[3];
    const float* dinit = (const float*)d_in[4];
    const float* Wmsg  = (const float*)d_in[5];
    const float* bmsg  = (const float*)d_in[6];
    const float* Wupd  = (const float*)d_in[7];
    const float* bupd  = (const float*)d_in[8];
    const float* Wedge = (const float*)d_in[9];
    const float* bedge = (const float*)d_in[10];
    float* out = (float*)d_out;
    (void)in_sizes; (void)n_in; (void)out_size;

    cudaFuncSetAttribute(edge_k, cudaFuncAttributeMaxDynamicSharedMemorySize, SMEM_EDGE);
    cudaFuncSetAttribute(node_k, cudaFuncAttributeMaxDynamicSharedMemorySize, 65536);
    cudaFuncSetAttribute(prep_k, cudaFuncAttributeMaxDynamicSharedMemorySize, 49152);

    zero_k<<<512, 256>>>();
    prep_k<<<(NN + 63) / 64, 256, 49152>>>(x, Wmsg);
    noop_k<<<1, 32>>>();   // keeps edge_k in the ncu capture slot (launch idx 3)
    edge_k<<<296, 256, SMEM_EDGE>>>(ei, ea, rr, dinit, Wmsg, bmsg, Wedge, bedge, out);
    node_k<<<(NN + 63) / 64, 256, 65536>>>(x, Wupd, bupd, out);
}

// round 16
// speedup vs baseline: 1.0220x; 1.0187x over previous
#include <cuda_runtime.h>
#include <cuda_bf16.h>
#include <math.h>
#include <stdint.h>

#define NN 50000
#define NE 800000
#define NSLICE (NE / 16)   // 50000 16-edge warp-slices

// ---------------- scratch (static device globals, no allocation) ----------------
__device__ float g_agg[(size_t)NN * 64];
__device__ float g_cnt[NN];
__device__ float g_P1[(size_t)NN * 64];
__device__ float g_P2[(size_t)NN * 64];
__device__ float g_P3[(size_t)NN * 64];

__global__ void zero_k() {
    int i = blockIdx.x * blockDim.x + threadIdx.x;
    int stride = gridDim.x * blockDim.x;
    for (int j = i; j < NN * 64; j += stride) g_agg[j] = 0.0f;
    for (int j = i; j < NN; j += stride) g_cnt[j] = 0.0f;
}

// no-op: keeps edge_k in the ncu-captured launch slot (absolute idx 3)
__global__ void noop_k() {}

// MUFU-free softplus: all FFMA/ALU, rel err ~1.5e-6.
__device__ __forceinline__ float softplus_f(float v) {
    float w = -fabsf(v);
    float t = fmaxf(w * 1.4426950408889634f, -120.0f);
    float nf = rintf(t);
    float f = t - nf;
    float g = f * 0.6931471805599453f;
    float p = 1.388888889e-3f;
    p = p * g + 8.333333333e-3f;
    p = p * g + 4.166666667e-2f;
    p = p * g + 1.666666667e-1f;
    p = p * g + 0.5f;
    p = p * g + 1.0f;
    p = p * g + 1.0f;
    int ni = __float2int_rn(nf);
    float scale = __int_as_float((127 + ni) << 23);
    float u = p * scale;
    float d = 2.0f + u;
    float y = 0.8249f - 0.16666667f * d;
    y = y * (2.0f - d * y);
    y = y * (2.0f - d * y);
    float z = u * y;
    float z2 = z * z;
    float q = 0.11111111f;
    q = q * z2 + 0.14285714f;
    q = q * z2 + 0.2f;
    q = q * z2 + 0.33333333f;
    q = q * z2 + 1.0f;
    float lg = 2.0f * z * q;
    return fmaxf(v, 0.0f) + lg;
}

__device__ __forceinline__ uint32_t smem_u32(const void* p) {
    uint32_t a;
    asm("{ .reg .u64 t; cvta.to.shared.u64 t, %1; cvt.u32.u64 %0, t; }" : "=r"(a) : "l"(p));
    return a;
}

__device__ __forceinline__ void red_add_v4(float* addr, float a, float b, float c, float d) {
    asm volatile("red.global.add.v4.f32 [%0], {%1, %2, %3, %4};"
                 :: "l"(addr), "f"(a), "f"(b), "f"(c), "f"(d) : "memory");
}

__device__ __forceinline__ void cp16(uint32_t dst, const void* src) {
    asm volatile("cp.async.cg.shared.global [%0], [%1], 16;" :: "r"(dst), "l"(src) : "memory");
}
#define CP_COMMIT() asm volatile("cp.async.commit_group;" ::: "memory")
#define CP_WAIT1()  asm volatile("cp.async.wait_group 1;" ::: "memory")

__device__ __forceinline__ void prefetch_l1(const void* p) {
    asm volatile("prefetch.global.L1 [%0];" :: "l"(p));
}

__device__ __forceinline__ uint32_t pack_hi(float a, float b, float& ra, float& rb) {
    __nv_bfloat16 ha = __float2bfloat16(a);
    __nv_bfloat16 hb = __float2bfloat16(b);
    ra = a - __bfloat162float(ha);
    rb = b - __bfloat162float(hb);
    return ((uint32_t)__bfloat16_as_ushort(hb) << 16) | (uint32_t)__bfloat16_as_ushort(ha);
}
__device__ __forceinline__ uint32_t pack_lo(float a, float b) {
    return ((uint32_t)__bfloat16_as_ushort(__float2bfloat16(b)) << 16) |
           (uint32_t)__bfloat16_as_ushort(__float2bfloat16(a));
}

__device__ __forceinline__ void ldsm4(uint32_t* r, uint32_t addr) {
    asm volatile("ldmatrix.sync.aligned.m8n8.x4.shared.b16 {%0,%1,%2,%3}, [%4];"
                 : "=r"(r[0]), "=r"(r[1]), "=r"(r[2]), "=r"(r[3]) : "r"(addr));
}
__device__ __forceinline__ void mma_bf16(float* d, const uint32_t* a, const uint32_t* b) {
    asm volatile(
        "mma.sync.aligned.m16n8k16.row.col.f32.bf16.bf16.f32 "
        "{%0,%1,%2,%3}, {%4,%5,%6,%7}, {%8,%9}, {%0,%1,%2,%3};"
        : "+f"(d[0]), "+f"(d[1]), "+f"(d[2]), "+f"(d[3])
        : "r"(a[0]), "r"(a[1]), "r"(a[2]), "r"(a[3]), "r"(b[0]), "r"(b[1]));
}

extern __shared__ char esm[];

// ---------------- prep: P1 = x@Wmsg[0:64], P2 = x@Wmsg[64:128], P3 = x@Wupd[0:64]+bupd ----------------
// smem: Wm[128*64]f @0 (32KB) | Wu[64*64]f @32768 (16KB) | xT[64*64]f @49152 (16KB) = 64KB
__global__ __launch_bounds__(256) void prep_k(const float* __restrict__ x,
                                              const float* __restrict__ Wmsg,
                                              const float* __restrict__ Wupd,
                                              const float* __restrict__ bupd) {
    float* Wm_s = (float*)esm;
    float* Wu_s = (float*)(esm + 32768);
    float* xT   = (float*)(esm + 49152);
    int tx = threadIdx.x;
    for (int i = tx; i < 2048; i += 256)
        ((float4*)Wm_s)[i] = ((const float4*)Wmsg)[i];
    for (int i = tx; i < 1024; i += 256)
        ((float4*)Wu_s)[i] = ((const float4*)Wupd)[i];

    int es = tx >> 2, part = tx & 3;
    int node = blockIdx.x * 64 + es;
    int nc = node < NN ? node : NN - 1;
    const float4* xp = (const float4*)(x + (size_t)nc * 64) + part * 4;
    #pragma unroll
    for (int i = 0; i < 4; i++) {
        float4 v = xp[i];
        int kb = part * 16 + i * 4;
        xT[(kb + 0) * 64 + es] = v.x; xT[(kb + 1) * 64 + es] = v.y;
        xT[(kb + 2) * 64 + es] = v.z; xT[(kb + 3) * 64 + es] = v.w;
    }
    __syncthreads();

    int c0 = (tx & 15) * 4, e0 = (tx >> 4) * 4;
    float a1[4][4], a2[4][4], a3[4][4];
    #pragma unroll
    for (int i = 0; i < 4; i++)
        #pragma unroll
        for (int j = 0; j < 4; j++) { a1[i][j] = 0.0f; a2[i][j] = 0.0f; a3[i][j] = 0.0f; }

    #pragma unroll 4
    for (int k = 0; k < 64; k++) {
        float4 f  = *(const float4*)(xT + k * 64 + e0);
        float4 w1 = *(const float4*)(Wm_s + k * 64 + c0);
        float4 w2 = *(const float4*)(Wm_s + (64 + k) * 64 + c0);
        float4 w3 = *(const float4*)(Wu_s + k * 64 + c0);
        a1[0][0] += f.x*w1.x; a1[0][1] += f.x*w1.y; a1[0][2] += f.x*w1.z; a1[0][3] += f.x*w1.w;
        a1[1][0] += f.y*w1.x; a1[1][1] += f.y*w1.y; a1[1][2] += f.y*w1.z; a1[1][3] += f.y*w1.w;
        a1[2][0] += f.z*w1.x; a1[2][1] += f.z*w1.y; a1[2][2] += f.z*w1.z; a1[2][3] += f.z*w1.w;
        a1[3][0] += f.w*w1.x; a1[3][1] += f.w*w1.y; a1[3][2] += f.w*w1.z; a1[3][3] += f.w*w1.w;
        a2[0][0] += f.x*w2.x; a2[0][1] += f.x*w2.y; a2[0][2] += f.x*w2.z; a2[0][3] += f.x*w2.w;
        a2[1][0] += f.y*w2.x; a2[1][1] += f.y*w2.y; a2[1][2] += f.y*w2.z; a2[1][3] += f.y*w2.w;
        a2[2][0] += f.z*w2.x; a2[2][1] += f.z*w2.y; a2[2][2] += f.z*w2.z; a2[2][3] += f.z*w2.w;
        a2[3][0] += f.w*w2.x; a2[3][1] += f.w*w2.y; a2[3][2] += f.w*w2.z; a2[3][3] += f.w*w2.w;
        a3[0][0] += f.x*w3.x; a3[0][1] += f.x*w3.y; a3[0][2] += f.x*w3.z; a3[0][3] += f.x*w3.w;
        a3[1][0] += f.y*w3.x; a3[1][1] += f.y*w3.y; a3[1][2] += f.y*w3.z; a3[1][3] += f.y*w3.w;
        a3[2][0] += f.z*w3.x; a3[2][1] += f.z*w3.y; a3[2][2] += f.z*w3.z; a3[2][3] += f.z*w3.w;
        a3[3][0] += f.w*w3.x; a3[3][1] += f.w*w3.y; a3[3][2] += f.w*w3.z; a3[3][3] += f.w*w3.w;
    }
    float4 bu = *(const float4*)(bupd + c0);
    #pragma unroll
    for (int i = 0; i < 4; i++) {
        int n = blockIdx.x * 64 + e0 + i;
        if (n < NN) {
            *(float4*)(g_P1 + (size_t)n * 64 + c0) = make_float4(a1[i][0], a1[i][1], a1[i][2], a1[i][3]);
            *(float4*)(g_P2 + (size_t)n * 64 + c0) = make_float4(a2[i][0], a2[i][1], a2[i][2], a2[i][3]);
            *(float4*)(g_P3 + (size_t)n * 64 + c0) = make_float4(
                a3[i][0] + bu.x, a3[i][1] + bu.y, a3[i][2] + bu.z, a3[i][3] + bu.w);
        }
    }
}

// ---------------- edge kernel: warp-independent slices + cp.async + P1/P2 L1-prefetch ----------------
#define ASTRIDE 272
#define O_B3   0                       // W3^T  [64n][hi128|lo128(+pad)]
#define O_BE   17408                   // We^T
#define O_A    34816                   // 8 warps x 2 bufs x 16 rows x 272B raw f32
#define O_SCAL 104448                  // 8 warps x 2 bufs x 320B (src16|dst16|rr32|di16)
#define O_WS   109568
#define O_BM   109824
#define O_BEB  110080
#define SMEM_EDGE 110336               // 2 CTAs/SM

__global__ __launch_bounds__(256, 2) void edge_k(
    const int* __restrict__ ei,
    const float* __restrict__ ea,
    const float* __restrict__ rr,
    const float* __restrict__ dinit,
    const float* __restrict__ Wmsg,
    const float* __restrict__ bmsg,
    const float* __restrict__ Wedge,
    const float* __restrict__ bedge,
    float* __restrict__ out)
{
    const int tx = threadIdx.x;
    const int wid = tx >> 5, lane = tx & 31;
    const uint32_t sb = smem_u32(esm);

    float* out_edge = out + (size_t)NN * 64;
    float* out_msg  = out + (size_t)NN * 64 + (size_t)NE * 64;
    float* out_str  = out + (size_t)NN * 64 + 2 * (size_t)NE * 64;

    // ---- one-time: stage W3^T, We^T as bf16 hi/lo ----
    for (int idx = tx; idx < 4096; idx += 256) {
        int n = idx >> 6, k = idx & 63;
        float w3 = Wmsg[(129 + k) * 64 + n];
        __nv_bfloat16 h = __float2bfloat16(w3);
        __nv_bfloat16 l = __float2bfloat16(w3 - __bfloat162float(h));
        *(__nv_bfloat16*)(esm + O_B3 + n * ASTRIDE + k * 2) = h;
        *(__nv_bfloat16*)(esm + O_B3 + n * ASTRIDE + 128 + k * 2) = l;
        float we = Wedge[k * 64 + n];
        h = __float2bfloat16(we);
        l = __float2bfloat16(we - __bfloat162float(h));
        *(__nv_bfloat16*)(esm + O_BE + n * ASTRIDE + k * 2) = h;
        *(__nv_bfloat16*)(esm + O_BE + n * ASTRIDE + 128 + k * 2) = l;
    }
    if (tx < 64) {
        ((float*)(esm + O_WS))[tx]  = Wmsg[128 * 64 + tx];
        ((float*)(esm + O_BM))[tx]  = bmsg[tx];
        ((float*)(esm + O_BEB))[tx] = bedge[tx];
    }
    __syncthreads();   // only block-wide sync

    // B fragment geometry
    const int q = lane >> 3, r = lane & 7;
    uint32_t b3c[4], bec[4];
    #pragma unroll
    for (int c = 0; c < 4; c++) {
        uint32_t brow = (uint32_t)(c * 16 + r + (q >> 1) * 8);
        b3c[c] = sb + O_B3 + brow * ASTRIDE + (q & 1) * 16;
        bec[c] = sb + O_BE + brow * ASTRIDE + (q & 1) * 16;
    }

    const int tg = lane >> 2;          // A fragment row group
    const int ci = lane & 3;           // A fragment k pair
    const int tc = ci * 2;
    const bool evenlane = (lane & 1) == 0;

    const uint32_t Abuf  = sb + O_A + (uint32_t)wid * 8704;      // + p*4352
    const uint32_t Sbuf  = sb + O_SCAL + (uint32_t)wid * 640;    // + p*320
    const char* Abase = esm + O_A + wid * 8704;
    const char* Sbase = esm + O_SCAL + wid * 640;

    const float* ws_s = (const float*)(esm + O_WS);
    const float* bm_s = (const float*)(esm + O_BM);
    const float* beb  = (const float*)(esm + O_BEB);

    // cp.async issue for one slice into buffer par (all 32 lanes)
    const int rowl = lane >> 1, chalf = (lane & 1) * 32;
    auto issue = [&](int sl, int par) {
        uint32_t ad = Abuf + par * 4352 + rowl * ASTRIDE + chalf * 4;
        const float* as = ea + (size_t)sl * 16 * 64 + rowl * 64 + chalf;
        #pragma unroll
        for (int i = 0; i < 8; i++) cp16(ad + i * 16, as + i * 4);
        uint32_t sd = Sbuf + par * 320;
        if (lane < 4)       cp16(sd + lane * 16,             ei + (size_t)sl * 16 + lane * 4);
        else if (lane < 8)  cp16(sd + 64 + (lane - 4) * 16,  ei + NE + (size_t)sl * 16 + (lane - 4) * 4);
        else if (lane < 16) cp16(sd + 128 + (lane - 8) * 16, rr + (size_t)sl * 32 + (lane - 8) * 4);
        else if (lane < 20) cp16(sd + 256 + (lane - 16) * 16, dinit + (size_t)sl * 16 + (lane - 16) * 4);
    };

    const int nwarps = gridDim.x * 8;
    int slice = blockIdx.x * 8 + wid;
    if (slice < NSLICE) issue(slice, 0);
    CP_COMMIT();

    int p = 0;
    for (; slice < NSLICE; slice += nwarps, p ^= 1) {
        __syncwarp();   // all lanes done reading buf p^1 from previous iteration
        int nxt = slice + nwarps;
        if (nxt < NSLICE) issue(nxt, p ^ 1);
        CP_COMMIT();
        CP_WAIT1();     // buf p complete (this thread)
        __syncwarp();   // cross-lane visibility of buf p

        const char* Ap = Abase + p * 4352;
        const int*   s_src = (const int*)(Sbase + p * 320);
        const int*   s_dst = s_src + 16;
        const float* s_rr  = (const float*)(s_dst + 16);
        const float* s_di  = s_rr + 32;

        // ---- L1 prefetch of exactly the P1/P2 sectors the epilogue will read ----
        {
            int rl0 = tg, rl1 = tg + 8;
            prefetch_l1(g_P1 + (size_t)s_src[rl0] * 64 + tc * 8);
            prefetch_l1(g_P2 + (size_t)s_dst[rl0] * 64 + tc * 8);
            prefetch_l1(g_P1 + (size_t)s_src[rl1] * 64 + tc * 8);
            prefetch_l1(g_P2 + (size_t)s_dst[rl1] * 64 + tc * 8);
        }

        // strain + count + out_str (lane<16)
        if (lane < 16) {
            float r0 = s_rr[2 * lane], r1 = s_rr[2 * lane + 1];
            float di = s_di[lane];
            float s = (sqrtf(r0 * r0 + r1 * r1) - di) / di;
            out_str[(size_t)slice * 16 + lane] = s;
            atomicAdd(&g_cnt[s_dst[lane]], 1.0f);
        }

        // ---- GEMM1: A frags built from raw f32 smem (LDS+pack), B via ldsm ----
        float acc[8][4];
        #pragma unroll
        for (int i = 0; i < 8; i++)
            #pragma unroll
            for (int j = 0; j < 4; j++) acc[i][j] = 0.0f;

        #pragma unroll
        for (int st = 0; st < 4; st++) {
            int koff = (st * 16 + tc) * 4;
            const char* rA = Ap + tg * ASTRIDE;
            const char* rB = Ap + (tg + 8) * ASTRIDE;
            float2 f0 = *(const float2*)(rA + koff);
            float2 f1 = *(const float2*)(rB + koff);
            float2 f2 = *(const float2*)(rA + koff + 32);
            float2 f3 = *(const float2*)(rB + koff + 32);
            uint32_t ah[4], al[4];
            float rx, ry;
            ah[0] = pack_hi(f0.x, f0.y, rx, ry); al[0] = pack_lo(rx, ry);
            ah[1] = pack_hi(f1.x, f1.y, rx, ry); al[1] = pack_lo(rx, ry);
            ah[2] = pack_hi(f2.x, f2.y, rx, ry); al[2] = pack_lo(rx, ry);
            ah[3] = pack_hi(f3.x, f3.y, rx, ry); al[3] = pack_lo(rx, ry);
            #pragma unroll
            for (int c = 0; c < 4; c++) {
                uint32_t bh[4], bl[4];
                ldsm4(bh, b3c[c] + st * 32);
                ldsm4(bl, b3c[c] + 128 + st * 32);
                mma_bf16(acc[2 * c],     ah, bh);   mma_bf16(acc[2 * c + 1], ah, bh + 2);
                mma_bf16(acc[2 * c],     al, bh);   mma_bf16(acc[2 * c + 1], al, bh + 2);
                mma_bf16(acc[2 * c],     ah, bl);   mma_bf16(acc[2 * c + 1], ah, bl + 2);
            }
        }

        // ---- epilogue 1: msg = softplus(acc + P1[src] + P2[dst] + s*ws + bm) ----
        uint32_t mh[16], ml[16];
        #pragma unroll
        for (int half = 0; half < 2; half++) {
            int rl = tg + half * 8;
            size_t e = (size_t)slice * 16 + rl;
            int src = s_src[rl];
            int dst = s_dst[rl];
            float r0 = s_rr[2 * rl], r1 = s_rr[2 * rl + 1];
            float di = s_di[rl];
            float s = (sqrtf(r0 * r0 + r1 * r1) - di) / di;
            const float* p1r = g_P1 + (size_t)src * 64;
            const float* p2r = g_P2 + (size_t)dst * 64;
            float* ap = g_agg + (size_t)dst * 64;
            #pragma unroll
            for (int nf = 0; nf < 8; nf++) {
                int n = nf * 8 + tc;
                float2 p1 = *(const float2*)(p1r + n);
                float2 p2 = *(const float2*)(p2r + n);
                float m0 = softplus_f(acc[nf][half * 2 + 0] + p1.x + p2.x + s * ws_s[n]     + bm_s[n]);
                float m1 = softplus_f(acc[nf][half * 2 + 1] + p1.y + p2.y + s * ws_s[n + 1] + bm_s[n + 1]);
                float q0, q1;
                mh[half * 8 + nf] = pack_hi(m0, m1, q0, q1);
                ml[half * 8 + nf] = pack_lo(q0, q1);
                float o0 = __shfl_xor_sync(0xFFFFFFFFu, m0, 1);
                float o1 = __shfl_xor_sync(0xFFFFFFFFu, m1, 1);
                if (evenlane) {
                    *(float4*)(out_msg + e * 64 + n) = make_float4(m0, m1, o0, o1);
                    red_add_v4(ap + n, m0, m1, o0, o1);
                }
            }
        }

        // ---- GEMM2: edge_new = msg @ Wedge; A-frags straight from mh/ml ----
        float a2[8][4];
        #pragma unroll
        for (int i = 0; i < 8; i++)
            #pragma unroll
            for (int j = 0; j < 4; j++) a2[i][j] = 0.0f;

        #pragma unroll
        for (int st = 0; st < 4; st++) {
            uint32_t ah[4] = { mh[2 * st], mh[8 + 2 * st], mh[2 * st + 1], mh[8 + 2 * st + 1] };
            uint32_t al[4] = { ml[2 * st], ml[8 + 2 * st], ml[2 * st + 1], ml[8 + 2 * st + 1] };
            #pragma unroll
            for (int c = 0; c < 4; c++) {
                uint32_t bh[4], bl[4];
                ldsm4(bh, bec[c] + st * 32);
                ldsm4(bl, bec[c] + 128 + st * 32);
                mma_bf16(a2[2 * c],     ah, bh);   mma_bf16(a2[2 * c + 1], ah, bh + 2);
                mma_bf16(a2[2 * c],     al, bh);   mma_bf16(a2[2 * c + 1], al, bh + 2);
                mma_bf16(a2[2 * c],     ah, bl);   mma_bf16(a2[2 * c + 1], ah, bl + 2);
            }
        }
        #pragma unroll
        for (int half = 0; half < 2; half++) {
            size_t e = (size_t)slice * 16 + tg + half * 8;
            #pragma unroll
            for (int nf = 0; nf < 8; nf++) {
                int n = nf * 8 + tc;
                float v0 = a2[nf][half * 2 + 0] + beb[n];
                float v1 = a2[nf][half * 2 + 1] + beb[n + 1];
                float o0 = __shfl_xor_sync(0xFFFFFFFFu, v0, 1);
                float o1 = __shfl_xor_sync(0xFFFFFFFFu, v1, 1);
                if (evenlane)
                    *(float4*)(out_edge + e * 64 + n) = make_float4(v0, v1, o0, o1);
            }
        }
    }
}

// ---------------- node update: x_new = P3 + (agg/max(cnt,1)) @ Wupd[64:128] ----------------
// smem: Wu2[64*64]f @0 (16KB) | fT[64*64]f @16384 (16KB)
__global__ __launch_bounds__(256) void node_k(
    const float* __restrict__ Wupd,
    float* __restrict__ out_x)
{
    float* W_s = (float*)esm;
    float* fT  = (float*)(esm + 16384);
    int tx = threadIdx.x;
    for (int i = tx; i < 1024; i += 256)
        ((float4*)W_s)[i] = ((const float4*)(Wupd + 64 * 64))[i];

    int es = tx >> 2, part = tx & 3;
    int node = blockIdx.x * 64 + es;
    int nc = node < NN ? node : NN - 1;
    float inv = 1.0f / fmaxf(g_cnt[nc], 1.0f);
    const float4* ap = (const float4*)(g_agg + (size_t)nc * 64) + part * 4;
    #pragma unroll
    for (int i = 0; i < 4; i++) {
        float4 w = ap[i];
        int kb = part * 16 + i * 4;
        fT[(kb + 0) * 64 + es] = w.x * inv; fT[(kb + 1) * 64 + es] = w.y * inv;
        fT[(kb + 2) * 64 + es] = w.z * inv; fT[(kb + 3) * 64 + es] = w.w * inv;
    }
    __syncthreads();

    int c0 = (tx & 15) * 4, e0 = (tx >> 4) * 4;
    float acc[4][4];
    #pragma unroll
    for (int i = 0; i < 4; i++)
        #pragma unroll
        for (int j = 0; j < 4; j++) acc[i][j] = 0.0f;

    #pragma unroll 8
    for (int k = 0; k < 64; k++) {
        float4 f = *(const float4*)(fT + k * 64 + e0);
        float4 w = *(const float4*)(W_s + k * 64 + c0);
        acc[0][0] += f.x*w.x; acc[0][1] += f.x*w.y; acc[0][2] += f.x*w.z; acc[0][3] += f.x*w.w;
        acc[1][0] += f.y*w.x; acc[1][1] += f.y*w.y; acc[1][2] += f.y*w.z; acc[1][3] += f.y*w.w;
        acc[2][0] += f.z*w.x; acc[2][1] += f.z*w.y; acc[2][2] += f.z*w.z; acc[2][3] += f.z*w.w;
        acc[3][0] += f.w*w.x; acc[3][1] += f.w*w.y; acc[3][2] += f.w*w.z; acc[3][3] += f.w*w.w;
    }
    #pragma unroll
    for (int i = 0; i < 4; i++) {
        int n = blockIdx.x * 64 + e0 + i;
        if (n < NN) {
            float4 p3 = *(const float4*)(g_P3 + (size_t)n * 64 + c0);
            *(float4*)(out_x + (size_t)n * 64 + c0) =
                make_float4(acc[i][0] + p3.x, acc[i][1] + p3.y, acc[i][2] + p3.z, acc[i][3] + p3.w);
        }
    }
}

extern "C" void kernel_launch(void* const* d_in, const int* in_sizes, int n_in,
                              void* d_out, int out_size) {
    const float* x     = (const float*)d_in[0];
    const int*   ei    = (const int*)d_in[1];
    const float* ea    = (const float*)d_in[2];
    const float* rr    = (const float*)d_in[3];
    const float* dinit = (const float*)d_in[4];
    const float* Wmsg  = (const float*)d_in[5];
    const float* bmsg  = (const float*)d_in[6];
    const float* Wupd  = (const float*)d_in[7];
    const float* bupd  = (const float*)d_in[8];
    const float* Wedge = (const float*)d_in[9];
    const float* bedge = (const float*)d_in[10];
    float* out = (float*)d_out;
    (void)in_sizes; (void)n_in; (void)out_size;

    cudaFuncSetAttribute(edge_k, cudaFuncAttributeMaxDynamicSharedMemorySize, SMEM_EDGE);
    cudaFuncSetAttribute(node_k, cudaFuncAttributeMaxDynamicSharedMemorySize, 32768);
    cudaFuncSetAttribute(prep_k, cudaFuncAttributeMaxDynamicSharedMemorySize, 65536);

    zero_k<<<512, 256>>>();
    prep_k<<<(NN + 63) / 64, 256, 65536>>>(x, Wmsg, Wupd, bupd);
    noop_k<<<1, 32>>>();   // keeps edge_k in the ncu capture slot (launch idx 3)
    edge_k<<<296, 256, SMEM_EDGE>>>(ei, ea, rr, dinit, Wmsg, bmsg, Wedge, bedge, out);
    node_k<<<(NN + 63) / 64, 256, 32768>>>(Wupd, out);
}

// round 17
// speedup vs baseline: 1.0243x; 1.0023x over previous
#include <cuda_runtime.h>
#include <cuda_bf16.h>
#include <math.h>
#include <stdint.h>

#define NN 50000
#define NE 800000
#define NSLICE (NE / 16)   // 50000 16-edge warp-slices

// ---------------- scratch (static device globals, no allocation) ----------------
__device__ float g_agg[(size_t)NN * 64];
__device__ float g_cnt[NN];
__device__ float g_P1[(size_t)NN * 64];
__device__ float g_P2[(size_t)NN * 64];
__device__ float g_P3[(size_t)NN * 64];

__global__ void zero_k() {
    int i = blockIdx.x * blockDim.x + threadIdx.x;
    int stride = gridDim.x * blockDim.x;
    for (int j = i; j < NN * 64; j += stride) g_agg[j] = 0.0f;
    for (int j = i; j < NN; j += stride) g_cnt[j] = 0.0f;
}

// no-op: keeps edge_k in the ncu-captured launch slot (absolute idx 3)
__global__ void noop_k() {}

// MUFU-free softplus: all FFMA/ALU, rel err ~1.5e-6.
__device__ __forceinline__ float softplus_f(float v) {
    float w = -fabsf(v);
    float t = fmaxf(w * 1.4426950408889634f, -120.0f);
    float nf = rintf(t);
    float f = t - nf;
    float g = f * 0.6931471805599453f;
    float p = 1.388888889e-3f;
    p = p * g + 8.333333333e-3f;
    p = p * g + 4.166666667e-2f;
    p = p * g + 1.666666667e-1f;
    p = p * g + 0.5f;
    p = p * g + 1.0f;
    p = p * g + 1.0f;
    int ni = __float2int_rn(nf);
    float scale = __int_as_float((127 + ni) << 23);
    float u = p * scale;
    float d = 2.0f + u;
    float y = 0.8249f - 0.16666667f * d;
    y = y * (2.0f - d * y);
    y = y * (2.0f - d * y);
    float z = u * y;
    float z2 = z * z;
    float q = 0.11111111f;
    q = q * z2 + 0.14285714f;
    q = q * z2 + 0.2f;
    q = q * z2 + 0.33333333f;
    q = q * z2 + 1.0f;
    float lg = 2.0f * z * q;
    return fmaxf(v, 0.0f) + lg;
}

__device__ __forceinline__ uint32_t smem_u32(const void* p) {
    uint32_t a;
    asm("{ .reg .u64 t; cvta.to.shared.u64 t, %1; cvt.u32.u64 %0, t; }" : "=r"(a) : "l"(p));
    return a;
}

__device__ __forceinline__ void red_add_v4(float* addr, float a, float b, float c, float d) {
    asm volatile("red.global.add.v4.f32 [%0], {%1, %2, %3, %4};"
                 :: "l"(addr), "f"(a), "f"(b), "f"(c), "f"(d) : "memory");
}

__device__ __forceinline__ void cp16(uint32_t dst, const void* src) {
    asm volatile("cp.async.cg.shared.global [%0], [%1], 16;" :: "r"(dst), "l"(src) : "memory");
}
#define CP_COMMIT() asm volatile("cp.async.commit_group;" ::: "memory")
#define CP_WAIT1()  asm volatile("cp.async.wait_group 1;" ::: "memory")

__device__ __forceinline__ void prefetch_l1(const void* p) {
    asm volatile("prefetch.global.L1 [%0];" :: "l"(p));
}

__device__ __forceinline__ uint32_t pack_hi(float a, float b, float& ra, float& rb) {
    __nv_bfloat16 ha = __float2bfloat16(a);
    __nv_bfloat16 hb = __float2bfloat16(b);
    ra = a - __bfloat162float(ha);
    rb = b - __bfloat162float(hb);
    return ((uint32_t)__bfloat16_as_ushort(hb) << 16) | (uint32_t)__bfloat16_as_ushort(ha);
}
__device__ __forceinline__ uint32_t pack_lo(float a, float b) {
    return ((uint32_t)__bfloat16_as_ushort(__float2bfloat16(b)) << 16) |
           (uint32_t)__bfloat16_as_ushort(__float2bfloat16(a));
}

__device__ __forceinline__ void ldsm4(uint32_t* r, uint32_t addr) {
    asm volatile("ldmatrix.sync.aligned.m8n8.x4.shared.b16 {%0,%1,%2,%3}, [%4];"
                 : "=r"(r[0]), "=r"(r[1]), "=r"(r[2]), "=r"(r[3]) : "r"(addr));
}
__device__ __forceinline__ void mma_bf16(float* d, const uint32_t* a, const uint32_t* b) {
    asm volatile(
        "mma.sync.aligned.m16n8k16.row.col.f32.bf16.bf16.f32 "
        "{%0,%1,%2,%3}, {%4,%5,%6,%7}, {%8,%9}, {%0,%1,%2,%3};"
        : "+f"(d[0]), "+f"(d[1]), "+f"(d[2]), "+f"(d[3])
        : "r"(a[0]), "r"(a[1]), "r"(a[2]), "r"(a[3]), "r"(b[0]), "r"(b[1]));
}

extern __shared__ char esm[];

// ---------------- prep: P1 = x@Wmsg[0:64], P2 = x@Wmsg[64:128], P3 = x@Wupd[0:64]+bupd ----------------
// smem: Wm[128*64]f @0 (32KB) | Wu[64*64]f @32768 (16KB) | xT[64*64]f @49152 (16KB) = 64KB
__global__ __launch_bounds__(256) void prep_k(const float* __restrict__ x,
                                              const float* __restrict__ Wmsg,
                                              const float* __restrict__ Wupd,
                                              const float* __restrict__ bupd) {
    float* Wm_s = (float*)esm;
    float* Wu_s = (float*)(esm + 32768);
    float* xT   = (float*)(esm + 49152);
    int tx = threadIdx.x;
    for (int i = tx; i < 2048; i += 256)
        ((float4*)Wm_s)[i] = ((const float4*)Wmsg)[i];
    for (int i = tx; i < 1024; i += 256)
        ((float4*)Wu_s)[i] = ((const float4*)Wupd)[i];

    int es = tx >> 2, part = tx & 3;
    int node = blockIdx.x * 64 + es;
    int nc = node < NN ? node : NN - 1;
    const float4* xp = (const float4*)(x + (size_t)nc * 64) + part * 4;
    #pragma unroll
    for (int i = 0; i < 4; i++) {
        float4 v = xp[i];
        int kb = part * 16 + i * 4;
        xT[(kb + 0) * 64 + es] = v.x; xT[(kb + 1) * 64 + es] = v.y;
        xT[(kb + 2) * 64 + es] = v.z; xT[(kb + 3) * 64 + es] = v.w;
    }
    __syncthreads();

    int c0 = (tx & 15) * 4, e0 = (tx >> 4) * 4;
    float a1[4][4], a2[4][4], a3[4][4];
    #pragma unroll
    for (int i = 0; i < 4; i++)
        #pragma unroll
        for (int j = 0; j < 4; j++) { a1[i][j] = 0.0f; a2[i][j] = 0.0f; a3[i][j] = 0.0f; }

    #pragma unroll 4
    for (int k = 0; k < 64; k++) {
        float4 f  = *(const float4*)(xT + k * 64 + e0);
        float4 w1 = *(const float4*)(Wm_s + k * 64 + c0);
        float4 w2 = *(const float4*)(Wm_s + (64 + k) * 64 + c0);
        float4 w3 = *(const float4*)(Wu_s + k * 64 + c0);
        a1[0][0] += f.x*w1.x; a1[0][1] += f.x*w1.y; a1[0][2] += f.x*w1.z; a1[0][3] += f.x*w1.w;
        a1[1][0] += f.y*w1.x; a1[1][1] += f.y*w1.y; a1[1][2] += f.y*w1.z; a1[1][3] += f.y*w1.w;
        a1[2][0] += f.z*w1.x; a1[2][1] += f.z*w1.y; a1[2][2] += f.z*w1.z; a1[2][3] += f.z*w1.w;
        a1[3][0] += f.w*w1.x; a1[3][1] += f.w*w1.y; a1[3][2] += f.w*w1.z; a1[3][3] += f.w*w1.w;
        a2[0][0] += f.x*w2.x; a2[0][1] += f.x*w2.y; a2[0][2] += f.x*w2.z; a2[0][3] += f.x*w2.w;
        a2[1][0] += f.y*w2.x; a2[1][1] += f.y*w2.y; a2[1][2] += f.y*w2.z; a2[1][3] += f.y*w2.w;
        a2[2][0] += f.z*w2.x; a2[2][1] += f.z*w2.y; a2[2][2] += f.z*w2.z; a2[2][3] += f.z*w2.w;
        a2[3][0] += f.w*w2.x; a2[3][1] += f.w*w2.y; a2[3][2] += f.w*w2.z; a2[3][3] += f.w*w2.w;
        a3[0][0] += f.x*w3.x; a3[0][1] += f.x*w3.y; a3[0][2] += f.x*w3.z; a3[0][3] += f.x*w3.w;
        a3[1][0] += f.y*w3.x; a3[1][1] += f.y*w3.y; a3[1][2] += f.y*w3.z; a3[1][3] += f.y*w3.w;
        a3[2][0] += f.z*w3.x; a3[2][1] += f.z*w3.y; a3[2][2] += f.z*w3.z; a3[2][3] += f.z*w3.w;
        a3[3][0] += f.w*w3.x; a3[3][1] += f.w*w3.y; a3[3][2] += f.w*w3.z; a3[3][3] += f.w*w3.w;
    }
    float4 bu = *(const float4*)(bupd + c0);
    #pragma unroll
    for (int i = 0; i < 4; i++) {
        int n = blockIdx.x * 64 + e0 + i;
        if (n < NN) {
            *(float4*)(g_P1 + (size_t)n * 64 + c0) = make_float4(a1[i][0], a1[i][1], a1[i][2], a1[i][3]);
            *(float4*)(g_P2 + (size_t)n * 64 + c0) = make_float4(a2[i][0], a2[i][1], a2[i][2], a2[i][3]);
            *(float4*)(g_P3 + (size_t)n * 64 + c0) = make_float4(
                a3[i][0] + bu.x, a3[i][1] + bu.y, a3[i][2] + bu.z, a3[i][3] + bu.w);
        }
    }
}

// ---------------- edge kernel: warp-independent slices + cp.async + P1/P2 L1-prefetch ----------------
#define ASTRIDE 272
#define O_B3   0                       // W3^T  [64n][hi128|lo128(+pad)]
#define O_BE   17408                   // We^T
#define O_A    34816                   // 8 warps x 2 bufs x 16 rows x 272B raw f32
#define O_SCAL 104448                  // 8 warps x 2 bufs x 320B (src16|dst16|rr32|di16)
#define O_WS   109568
#define O_BM   109824
#define O_BEB  110080
#define SMEM_EDGE 110336               // 2 CTAs/SM

__global__ __launch_bounds__(256, 2) void edge_k(
    const int* __restrict__ ei,
    const float* __restrict__ ea,
    const float* __restrict__ rr,
    const float* __restrict__ dinit,
    const float* __restrict__ Wmsg,
    const float* __restrict__ bmsg,
    const float* __restrict__ Wedge,
    const float* __restrict__ bedge,
    float* __restrict__ out)
{
    const int tx = threadIdx.x;
    const int wid = tx >> 5, lane = tx & 31;
    const uint32_t sb = smem_u32(esm);

    float* out_edge = out + (size_t)NN * 64;
    float* out_msg  = out + (size_t)NN * 64 + (size_t)NE * 64;
    float* out_str  = out + (size_t)NN * 64 + 2 * (size_t)NE * 64;

    // ---- one-time: stage W3^T, We^T as bf16 hi/lo ----
    for (int idx = tx; idx < 4096; idx += 256) {
        int n = idx >> 6, k = idx & 63;
        float w3 = Wmsg[(129 + k) * 64 + n];
        __nv_bfloat16 h = __float2bfloat16(w3);
        __nv_bfloat16 l = __float2bfloat16(w3 - __bfloat162float(h));
        *(__nv_bfloat16*)(esm + O_B3 + n * ASTRIDE + k * 2) = h;
        *(__nv_bfloat16*)(esm + O_B3 + n * ASTRIDE + 128 + k * 2) = l;
        float we = Wedge[k * 64 + n];
        h = __float2bfloat16(we);
        l = __float2bfloat16(we - __bfloat162float(h));
        *(__nv_bfloat16*)(esm + O_BE + n * ASTRIDE + k * 2) = h;
        *(__nv_bfloat16*)(esm + O_BE + n * ASTRIDE + 128 + k * 2) = l;
    }
    if (tx < 64) {
        ((float*)(esm + O_WS))[tx]  = Wmsg[128 * 64 + tx];
        ((float*)(esm + O_BM))[tx]  = bmsg[tx];
        ((float*)(esm + O_BEB))[tx] = bedge[tx];
    }
    __syncthreads();   // only block-wide sync

    // B fragment geometry
    const int q = lane >> 3, r = lane & 7;
    uint32_t b3c[4], bec[4];
    #pragma unroll
    for (int c = 0; c < 4; c++) {
        uint32_t brow = (uint32_t)(c * 16 + r + (q >> 1) * 8);
        b3c[c] = sb + O_B3 + brow * ASTRIDE + (q & 1) * 16;
        bec[c] = sb + O_BE + brow * ASTRIDE + (q & 1) * 16;
    }

    const int tg = lane >> 2;          // A fragment row group
    const int ci = lane & 3;           // A fragment k pair
    const int tc = ci * 2;
    const bool evenlane = (lane & 1) == 0;

    const uint32_t Abuf  = sb + O_A + (uint32_t)wid * 8704;      // + p*4352
    const uint32_t Sbuf  = sb + O_SCAL + (uint32_t)wid * 640;    // + p*320
    const char* Abase = esm + O_A + wid * 8704;
    const char* Sbase = esm + O_SCAL + wid * 640;

    const float* ws_s = (const float*)(esm + O_WS);
    const float* bm_s = (const float*)(esm + O_BM);
    const float* beb  = (const float*)(esm + O_BEB);

    // cp.async issue for one slice into buffer par (all 32 lanes)
    const int rowl = lane >> 1, chalf = (lane & 1) * 32;
    auto issue = [&](int sl, int par) {
        uint32_t ad = Abuf + par * 4352 + rowl * ASTRIDE + chalf * 4;
        const float* as = ea + (size_t)sl * 16 * 64 + rowl * 64 + chalf;
        #pragma unroll
        for (int i = 0; i < 8; i++) cp16(ad + i * 16, as + i * 4);
        uint32_t sd = Sbuf + par * 320;
        if (lane < 4)       cp16(sd + lane * 16,             ei + (size_t)sl * 16 + lane * 4);
        else if (lane < 8)  cp16(sd + 64 + (lane - 4) * 16,  ei + NE + (size_t)sl * 16 + (lane - 4) * 4);
        else if (lane < 16) cp16(sd + 128 + (lane - 8) * 16, rr + (size_t)sl * 32 + (lane - 8) * 4);
        else if (lane < 20) cp16(sd + 256 + (lane - 16) * 16, dinit + (size_t)sl * 16 + (lane - 16) * 4);
    };

    const int nwarps = gridDim.x * 8;
    int slice = blockIdx.x * 8 + wid;
    if (slice < NSLICE) issue(slice, 0);
    CP_COMMIT();

    int p = 0;
    for (; slice < NSLICE; slice += nwarps, p ^= 1) {
        __syncwarp();   // all lanes done reading buf p^1 from previous iteration
        int nxt = slice + nwarps;
        if (nxt < NSLICE) issue(nxt, p ^ 1);
        CP_COMMIT();
        CP_WAIT1();     // buf p complete (this thread)
        __syncwarp();   // cross-lane visibility of buf p

        const char* Ap = Abase + p * 4352;
        const int*   s_src = (const int*)(Sbase + p * 320);
        const int*   s_dst = s_src + 16;
        const float* s_rr  = (const float*)(s_dst + 16);
        const float* s_di  = s_rr + 32;

        // ---- L1 prefetch of exactly the P1/P2 sectors the epilogue will read ----
        {
            int rl0 = tg, rl1 = tg + 8;
            prefetch_l1(g_P1 + (size_t)s_src[rl0] * 64 + tc * 8);
            prefetch_l1(g_P2 + (size_t)s_dst[rl0] * 64 + tc * 8);
            prefetch_l1(g_P1 + (size_t)s_src[rl1] * 64 + tc * 8);
            prefetch_l1(g_P2 + (size_t)s_dst[rl1] * 64 + tc * 8);
        }

        // strain + count + out_str (lane<16)
        if (lane < 16) {
            float r0 = s_rr[2 * lane], r1 = s_rr[2 * lane + 1];
            float di = s_di[lane];
            float s = (sqrtf(r0 * r0 + r1 * r1) - di) / di;
            out_str[(size_t)slice * 16 + lane] = s;
            atomicAdd(&g_cnt[s_dst[lane]], 1.0f);
        }

        // ---- GEMM1: A frags built from raw f32 smem (LDS+pack), B via ldsm ----
        float acc[8][4];
        #pragma unroll
        for (int i = 0; i < 8; i++)
            #pragma unroll
            for (int j = 0; j < 4; j++) acc[i][j] = 0.0f;

        #pragma unroll
        for (int st = 0; st < 4; st++) {
            int koff = (st * 16 + tc) * 4;
            const char* rA = Ap + tg * ASTRIDE;
            const char* rB = Ap + (tg + 8) * ASTRIDE;
            float2 f0 = *(const float2*)(rA + koff);
            float2 f1 = *(const float2*)(rB + koff);
            float2 f2 = *(const float2*)(rA + koff + 32);
            float2 f3 = *(const float2*)(rB + koff + 32);
            uint32_t ah[4], al[4];
            float rx, ry;
            ah[0] = pack_hi(f0.x, f0.y, rx, ry); al[0] = pack_lo(rx, ry);
            ah[1] = pack_hi(f1.x, f1.y, rx, ry); al[1] = pack_lo(rx, ry);
            ah[2] = pack_hi(f2.x, f2.y, rx, ry); al[2] = pack_lo(rx, ry);
            ah[3] = pack_hi(f3.x, f3.y, rx, ry); al[3] = pack_lo(rx, ry);
            #pragma unroll
            for (int c = 0; c < 4; c++) {
                uint32_t bh[4], bl[4];
                ldsm4(bh, b3c[c] + st * 32);
                ldsm4(bl, b3c[c] + 128 + st * 32);
                mma_bf16(acc[2 * c],     ah, bh);   mma_bf16(acc[2 * c + 1], ah, bh + 2);
                mma_bf16(acc[2 * c],     al, bh);   mma_bf16(acc[2 * c + 1], al, bh + 2);
                mma_bf16(acc[2 * c],     ah, bl);   mma_bf16(acc[2 * c + 1], ah, bl + 2);
            }
        }

        // ---- epilogue 1: msg = softplus(acc + P1[src] + P2[dst] + s*ws + bm) ----
        uint32_t mh[16], ml[16];
        #pragma unroll
        for (int half = 0; half < 2; half++) {
            int rl = tg + half * 8;
            size_t e = (size_t)slice * 16 + rl;
            int src = s_src[rl];
            int dst = s_dst[rl];
            float r0 = s_rr[2 * rl], r1 = s_rr[2 * rl + 1];
            float di = s_di[rl];
            float s = (sqrtf(r0 * r0 + r1 * r1) - di) / di;
            const float* p1r = g_P1 + (size_t)src * 64;
            const float* p2r = g_P2 + (size_t)dst * 64;
            float* ap = g_agg + (size_t)dst * 64;
            #pragma unroll
            for (int nf = 0; nf < 8; nf++) {
                int n = nf * 8 + tc;
                float2 p1 = *(const float2*)(p1r + n);
                float2 p2 = *(const float2*)(p2r + n);
                float m0 = softplus_f(acc[nf][half * 2 + 0] + p1.x + p2.x + s * ws_s[n]     + bm_s[n]);
                float m1 = softplus_f(acc[nf][half * 2 + 1] + p1.y + p2.y + s * ws_s[n + 1] + bm_s[n + 1]);
                float q0, q1;
                mh[half * 8 + nf] = pack_hi(m0, m1, q0, q1);
                ml[half * 8 + nf] = pack_lo(q0, q1);
                float o0 = __shfl_xor_sync(0xFFFFFFFFu, m0, 1);
                float o1 = __shfl_xor_sync(0xFFFFFFFFu, m1, 1);
                if (evenlane) {
                    *(float4*)(out_msg + e * 64 + n) = make_float4(m0, m1, o0, o1);
                    red_add_v4(ap + n, m0, m1, o0, o1);
                }
            }
        }

        // ---- GEMM2: edge_new = msg @ Wedge; A-frags straight from mh/ml ----
        float a2[8][4];
        #pragma unroll
        for (int i = 0; i < 8; i++)
            #pragma unroll
            for (int j = 0; j < 4; j++) a2[i][j] = 0.0f;

        #pragma unroll
        for (int st = 0; st < 4; st++) {
            uint32_t ah[4] = { mh[2 * st], mh[8 + 2 * st], mh[2 * st + 1], mh[8 + 2 * st + 1] };
            uint32_t al[4] = { ml[2 * st], ml[8 + 2 * st], ml[2 * st + 1], ml[8 + 2 * st + 1] };
            #pragma unroll
            for (int c = 0; c < 4; c++) {
                uint32_t bh[4], bl[4];
                ldsm4(bh, bec[c] + st * 32);
                ldsm4(bl, bec[c] + 128 + st * 32);
                mma_bf16(a2[2 * c],     ah, bh);   mma_bf16(a2[2 * c + 1], ah, bh + 2);
                mma_bf16(a2[2 * c],     al, bh);   mma_bf16(a2[2 * c + 1], al, bh + 2);
                mma_bf16(a2[2 * c],     ah, bl);   mma_bf16(a2[2 * c + 1], ah, bl + 2);
            }
        }
        #pragma unroll
        for (int half = 0; half < 2; half++) {
            size_t e = (size_t)slice * 16 + tg + half * 8;
            #pragma unroll
            for (int nf = 0; nf < 8; nf++) {
                int n = nf * 8 + tc;
                float v0 = a2[nf][half * 2 + 0] + beb[n];
                float v1 = a2[nf][half * 2 + 1] + beb[n + 1];
                float o0 = __shfl_xor_sync(0xFFFFFFFFu, v0, 1);
                float o1 = __shfl_xor_sync(0xFFFFFFFFu, v1, 1);
                if (evenlane)
                    *(float4*)(out_edge + e * 64 + n) = make_float4(v0, v1, o0, o1);
            }
        }
    }
}

// ---------------- node update: x_new = P3 + (agg/max(cnt,1)) @ Wupd[64:128] ----------------
// smem: Wu2[64*64]f @0 (16KB) | fT[64*64]f @16384 (16KB)
__global__ __launch_bounds__(256) void node_k(
    const float* __restrict__ Wupd,
    float* __restrict__ out_x)
{
    float* W_s = (float*)esm;
    float* fT  = (float*)(esm + 16384);
    int tx = threadIdx.x;
    for (int i = tx; i < 1024; i += 256)
        ((float4*)W_s)[i] = ((const float4*)(Wupd + 64 * 64))[i];

    int es = tx >> 2, part = tx & 3;
    int node = blockIdx.x * 64 + es;
    int nc = node < NN ? node : NN - 1;
    float inv = 1.0f / fmaxf(g_cnt[nc], 1.0f);
    const float4* ap = (const float4*)(g_agg + (size_t)nc * 64) + part * 4;
    #pragma unroll
    for (int i = 0; i < 4; i++) {
        float4 w = ap[i];
        int kb = part * 16 + i * 4;
        fT[(kb + 0) * 64 + es] = w.x * inv; fT[(kb + 1) * 64 + es] = w.y * inv;
        fT[(kb + 2) * 64 + es] = w.z * inv; fT[(kb + 3) * 64 + es] = w.w * inv;
    }
    __syncthreads();

    int c0 = (tx & 15) * 4, e0 = (tx >> 4) * 4;
    float acc[4][4];
    #pragma unroll
    for (int i = 0; i < 4; i++)
        #pragma unroll
        for (int j = 0; j < 4; j++) acc[i][j] = 0.0f;

    #pragma unroll 8
    for (int k = 0; k < 64; k++) {
        float4 f = *(const float4*)(fT + k * 64 + e0);
        float4 w = *(const float4*)(W_s + k * 64 + c0);
        acc[0][0] += f.x*w.x; acc[0][1] += f.x*w.y; acc[0][2] += f.x*w.z; acc[0][3] += f.x*w.w;
        acc[1][0] += f.y*w.x; acc[1][1] += f.y*w.y; acc[1][2] += f.y*w.z; acc[1][3] += f.y*w.w;
        acc[2][0] += f.z*w.x; acc[2][1] += f.z*w.y; acc[2][2] += f.z*w.z; acc[2][3] += f.z*w.w;
        acc[3][0] += f.w*w.x; acc[3][1] += f.w*w.y; acc[3][2] += f.w*w.z; acc[3][3] += f.w*w.w;
    }
    #pragma unroll
    for (int i = 0; i < 4; i++) {
        int n = blockIdx.x * 64 + e0 + i;
        if (n < NN) {
            float4 p3 = *(const float4*)(g_P3 + (size_t)n * 64 + c0);
            *(float4*)(out_x + (size_t)n * 64 + c0) =
                make_float4(acc[i][0] + p3.x, acc[i][1] + p3.y, acc[i][2] + p3.z, acc[i][3] + p3.w);
        }
    }
}

extern "C" void kernel_launch(void* const* d_in, const int* in_sizes, int n_in,
                              void* d_out, int out_size) {
    const float* x     = (const float*)d_in[0];
    const int*   ei    = (const int*)d_in[1];
    const float* ea    = (const float*)d_in[2];
    const float* rr    = (const float*)d_in[3];
    const float* dinit = (const float*)d_in[4];
    const float* Wmsg  = (const float*)d_in[5];
    const float* bmsg  = (const float*)d_in[6];
    const float* Wupd  = (const float*)d_in[7];
    const float* bupd  = (const float*)d_in[8];
    const float* Wedge = (const float*)d_in[9];
    const float* bedge = (const float*)d_in[10];
    float* out = (float*)d_out;
    (void)in_sizes; (void)n_in; (void)out_size;

    cudaFuncSetAttribute(edge_k, cudaFuncAttributeMaxDynamicSharedMemorySize, SMEM_EDGE);
    cudaFuncSetAttribute(node_k, cudaFuncAttributeMaxDynamicSharedMemorySize, 32768);
    cudaFuncSetAttribute(prep_k, cudaFuncAttributeMaxDynamicSharedMemorySize, 65536);

    zero_k<<<512, 256>>>();
    prep_k<<<(NN + 63) / 64, 256, 65536>>>(x, Wmsg, Wupd, bupd);
    noop_k<<<1, 32>>>();   // keeps edge_k in the ncu capture slot (launch idx 3)
    edge_k<<<296, 256, SMEM_EDGE>>>(ei, ea, rr, dinit, Wmsg, bmsg, Wedge, bedge, out);
    node_k<<<(NN + 63) / 64, 256, 32768>>>(Wupd, out);
}